// round 10
// baseline (speedup 1.0000x reference)
#include <cuda_runtime.h>
#include <cuda_fp16.h>
#include <math.h>
#include <stdint.h>

// Problem constants (fixed by the reference)
#define NN 100000
#define NE 3200000
#define H1 4
#define D1 128
#define F1 512     // H1*D1
#define F2 64
#define NEG_SLOPE 0.2f

// ---------------- scratch (static __device__ arrays; allocation is forbidden) ----------------
__device__ __align__(16) __half g_xh[(size_t)NN * D1];      // x in fp16 (25.6 MB)
__device__ __align__(16) __half g_w1h[D1 * F1];             // W1 fp16
__device__ __align__(16) __half g_w2h[F1 * F2];             // W2 fp16
__device__ __align__(16) __half g_feat1h[(size_t)NN * F1];  // layer1 linear out, HEAD-MAJOR [H][N][128]
__device__ __align__(16) __half g_h1h[(size_t)NN * F1];     // ELU(agg1) fp16, node-major [N][512]
__device__ __align__(16) __half g_feat2h[(size_t)NN * F2];  // layer2 linear out fp16 (12.8 MB)
__device__ float g_el1[H1 * NN];           // HEAD-MAJOR [H][N]
__device__ float g_er1[NN * H1];           // node-major
__device__ float g_el2[NN],      g_er2[NN];
__device__ int g_src32[NE], g_dst32[NE];   // int32 index mirrors (coalesced scatter)
__device__ int g_ssrc[NE];                 // src id per CSR slot
__device__ int g_deg[NN];
__device__ int g_rowptr[NN + 1];
__device__ int g_cursor[NN];
__device__ int g_mode;                     // 0 = int64 indices, 1 = int32 indices

// ---------------- helpers ----------------
__device__ __forceinline__ float lrelu(float x) { return x >= 0.f ? x : NEG_SLOPE * x; }

__device__ __forceinline__ void ldsm_x4(uint32_t r[4], uint32_t addr) {
    asm volatile("ldmatrix.sync.aligned.m8n8.x4.shared.b16 {%0,%1,%2,%3}, [%4];"
                 : "=r"(r[0]), "=r"(r[1]), "=r"(r[2]), "=r"(r[3]) : "r"(addr));
}
__device__ __forceinline__ void ldsm_x4_t(uint32_t r[4], uint32_t addr) {
    asm volatile("ldmatrix.sync.aligned.m8n8.x4.trans.shared.b16 {%0,%1,%2,%3}, [%4];"
                 : "=r"(r[0]), "=r"(r[1]), "=r"(r[2]), "=r"(r[3]) : "r"(addr));
}
__device__ __forceinline__ void mma16816(float c[4], const uint32_t a[4], const uint32_t b[2]) {
    asm volatile("mma.sync.aligned.m16n8k16.row.col.f32.f16.f16.f32 "
                 "{%0,%1,%2,%3}, {%4,%5,%6,%7}, {%8,%9}, {%0,%1,%2,%3};"
                 : "+f"(c[0]), "+f"(c[1]), "+f"(c[2]), "+f"(c[3])
                 : "r"(a[0]), "r"(a[1]), "r"(a[2]), "r"(a[3]), "r"(b[0]), "r"(b[1]));
}
__device__ __forceinline__ void cp16(uint32_t smem, const void* g) {
    asm volatile("cp.async.cg.shared.global [%0], [%1], 16;" :: "r"(smem), "l"(g));
}
__device__ __forceinline__ void cp_commit() { asm volatile("cp.async.commit_group;"); }
__device__ __forceinline__ void cp_wait1() { asm volatile("cp.async.wait_group 1;"); }
__device__ __forceinline__ void cp_wait0() { asm volatile("cp.async.wait_group 0;"); }

// ---------------- launch 1: detect index width + zero deg/score accumulators ----------------
__global__ void k_setup0(const long long* __restrict__ src) {
    if (blockIdx.x == 0) {
        if (threadIdx.x == 0) {
            int m = 0;
            for (int i = 0; i < 256; i++) {
                long long v = src[i];
                if (v < 0 || v >= NN) { m = 1; break; }
            }
            g_mode = m;
        }
        return;
    }
    int i = (blockIdx.x - 1) * blockDim.x + threadIdx.x;
    if (i < NN * H1) { g_el1[i] = 0.f; g_er1[i] = 0.f; }
    if (i < NN) { g_deg[i] = 0; g_el2[i] = 0.f; g_er2[i] = 0.f; }
}

// ---------------- launch 2: conv (index widen + degree hist) || cast (fp32->fp16) ----------
__device__ __forceinline__ uint2 f4toh(float4 v) {
    __half2 a = __floats2half2_rn(v.x, v.y);
    __half2 b = __floats2half2_rn(v.z, v.w);
    uint2 r;
    r.x = *(uint32_t*)&a;
    r.y = *(uint32_t*)&b;
    return r;
}
#define EBLK 12500
__global__ void k_setup1(const float4* __restrict__ x, const float4* __restrict__ w1,
                         const float4* __restrict__ w2,
                         const void* __restrict__ srcp, const void* __restrict__ dstp) {
    if (blockIdx.x < EBLK) {
        // conv
        int i = blockIdx.x * blockDim.x + threadIdx.x;
        if (i >= NE) return;
        int s, d;
        if (g_mode) {
            s = ((const int*)srcp)[i];
            d = ((const int*)dstp)[i];
        } else {
            s = (int)((const long long*)srcp)[i];
            d = (int)((const long long*)dstp)[i];
        }
        g_src32[i] = s;
        g_dst32[i] = d;
        atomicAdd(&g_deg[d], 1);
    } else {
        // cast
        int i = (blockIdx.x - EBLK) * blockDim.x + threadIdx.x;
        if (i < NN * D1 / 4) ((uint2*)g_xh)[i]  = f4toh(x[i]);
        if (i < D1 * F1 / 4) ((uint2*)g_w1h)[i] = f4toh(w1[i]);
        if (i < F1 * F2 / 4) ((uint2*)g_w2h)[i] = f4toh(w2[i]);
    }
}

// ---------------- launch 3: parallel exclusive scan of degrees ----------------
__global__ __launch_bounds__(1024) void k_scan() {
    const int PER = (NN + 1023) / 1024;  // 98
    int tid = threadIdx.x, lane = tid & 31, wid = tid >> 5;
    int base = tid * PER;
    int sum = 0;
    for (int j = 0; j < PER; j++) {
        int i = base + j;
        if (i < NN) sum += g_deg[i];
    }
    int incl = sum;
    #pragma unroll
    for (int o = 1; o < 32; o <<= 1) {
        int t = __shfl_up_sync(0xffffffffu, incl, o);
        if (lane >= o) incl += t;
    }
    __shared__ int wsum[32];
    if (lane == 31) wsum[wid] = incl;
    __syncthreads();
    if (wid == 0) {
        int v = wsum[lane];
        int z = v;
        #pragma unroll
        for (int o = 1; o < 32; o <<= 1) {
            int t = __shfl_up_sync(0xffffffffu, z, o);
            if (lane >= o) z += t;
        }
        wsum[lane] = z - v;
    }
    __syncthreads();
    int run = incl - sum + wsum[wid];
    for (int j = 0; j < PER; j++) {
        int i = base + j;
        if (i < NN) {
            g_rowptr[i] = run;
            g_cursor[i] = run;
            run += g_deg[i];
        }
    }
    if (tid == 1023) g_rowptr[NN] = run;
}

// ---------------- HMMA fp16 GEMM, cp.async double-buffered, fused score epilogue ----------
// BM=128, BN=64, BK=32; 8 warps (4m x 2n), 32x32 per warp.
// OUTMODE 1: fp16 head-major C ([H][NN][128]); scores -> el1 (head-major), er1 (node-major)
// OUTMODE 2: fp16 node-major C ([NN][64]);      scores -> el2, er2
template<int K, int N, int OUTMODE>
__device__ __forceinline__ void gemm_body(const __half* __restrict__ A,
                                          const __half* __restrict__ B,
                                          __half* __restrict__ Ch, int M,
                                          const float* __restrict__ al,
                                          const float* __restrict__ ar,
                                          int rowBase, int colBase) {
    __shared__ __half As[2][128][40];  // +8 pad
    __shared__ __half Bs[2][32][72];   // +8 pad
    int tid = threadIdx.x;
    int lane = tid & 31, wid = tid >> 5;
    int wm = wid >> 1, wn = wid & 1;

    float acc[2][4][4];
    #pragma unroll
    for (int a = 0; a < 2; a++)
        #pragma unroll
        for (int b = 0; b < 4; b++)
            #pragma unroll
            for (int c = 0; c < 4; c++) acc[a][b][c] = 0.f;

    uint32_t as_base = (uint32_t)__cvta_generic_to_shared(&As[0][0][0]);
    uint32_t bs_base = (uint32_t)__cvta_generic_to_shared(&Bs[0][0][0]);

    auto load_tiles = [&](int kt, int b) {
        #pragma unroll
        for (int hh = 0; hh < 2; hh++) {
            int r = (tid >> 2) + hh * 64;
            int grow = rowBase + r;
            if (grow >= M) grow = M - 1;
            cp16(as_base + (uint32_t)(((b << 7) + r) * 40 + (tid & 3) * 8) * 2,
                 A + (size_t)grow * K + kt + (tid & 3) * 8);
        }
        int r = tid >> 3, c = (tid & 7) * 8;
        cp16(bs_base + (uint32_t)(((b << 5) + r) * 72 + c) * 2,
             B + (size_t)(kt + r) * N + colBase + c);
    };

    int g = lane >> 3;
    int arow_l = (lane & 7) + ((g & 1) ? 8 : 0);
    int acol_l = (g & 2) ? 8 : 0;
    int brow_l = ((g & 1) ? 8 : 0) + (lane & 7);
    int bcol_l = (g & 2) ? 8 : 0;

    const int NIT = K / 32;
    load_tiles(0, 0);
    cp_commit();
    int buf = 0;
    for (int it = 0; it < NIT; it++) {
        if (it + 1 < NIT) {
            load_tiles((it + 1) * 32, buf ^ 1);
            cp_commit();
            cp_wait1();
        } else {
            cp_wait0();
        }
        __syncthreads();
        #pragma unroll
        for (int kk = 0; kk < 2; kk++) {
            uint32_t af[2][4], bf[4][2];
            #pragma unroll
            for (int mi = 0; mi < 2; mi++) {
                int arow = wm * 32 + mi * 16 + arow_l;
                int acol = kk * 16 + acol_l;
                ldsm_x4(af[mi], as_base + (uint32_t)(((buf << 7) + arow) * 40 + acol) * 2);
            }
            #pragma unroll
            for (int n2 = 0; n2 < 2; n2++) {
                int kr = kk * 16 + brow_l;
                int nc = wn * 32 + n2 * 16 + bcol_l;
                uint32_t r4[4];
                ldsm_x4_t(r4, bs_base + (uint32_t)(((buf << 5) + kr) * 72 + nc) * 2);
                bf[n2 * 2][0] = r4[0]; bf[n2 * 2][1] = r4[1];
                bf[n2 * 2 + 1][0] = r4[2]; bf[n2 * 2 + 1][1] = r4[3];
            }
            #pragma unroll
            for (int mi = 0; mi < 2; mi++)
                #pragma unroll
                for (int nf = 0; nf < 4; nf++)
                    mma16816(acc[mi][nf], af[mi], bf[nf]);
        }
        __syncthreads();
        buf ^= 1;
    }

    int lr = lane >> 2, lc = (lane & 3) * 2;

    // ---- store C + accumulate per-row score partials ----
    float sel[4] = {0.f, 0.f, 0.f, 0.f};   // rows: wm*32 + {lr, lr+8, 16+lr, 24+lr}
    float ser[4] = {0.f, 0.f, 0.f, 0.f};
    #pragma unroll
    for (int mi = 0; mi < 2; mi++) {
        #pragma unroll
        for (int nf = 0; nf < 4; nf++) {
            int r0 = rowBase + wm * 32 + mi * 16 + lr;
            int cc = colBase + wn * 32 + nf * 8 + lc;
            float a0, a1, r0a, r1a;
            if constexpr (OUTMODE == 1) {
                int h = cc >> 7, d = cc & 127;
                a0 = __ldg(&al[h * 128 + d]);     a1 = __ldg(&al[h * 128 + d + 1]);
                r0a = __ldg(&ar[h * 128 + d]);    r1a = __ldg(&ar[h * 128 + d + 1]);
                if (r0 < M)
                    *(__half2*)(Ch + ((size_t)h * NN + r0) * 128 + d) =
                        __floats2half2_rn(acc[mi][nf][0], acc[mi][nf][1]);
                if (r0 + 8 < M)
                    *(__half2*)(Ch + ((size_t)h * NN + r0 + 8) * 128 + d) =
                        __floats2half2_rn(acc[mi][nf][2], acc[mi][nf][3]);
            } else {
                a0 = __ldg(&al[cc]);  a1 = __ldg(&al[cc + 1]);
                r0a = __ldg(&ar[cc]); r1a = __ldg(&ar[cc + 1]);
                if (r0 < M)
                    *(__half2*)(Ch + (size_t)r0 * N + cc) =
                        __floats2half2_rn(acc[mi][nf][0], acc[mi][nf][1]);
                if (r0 + 8 < M)
                    *(__half2*)(Ch + (size_t)(r0 + 8) * N + cc) =
                        __floats2half2_rn(acc[mi][nf][2], acc[mi][nf][3]);
            }
            sel[mi * 2]     += acc[mi][nf][0] * a0  + acc[mi][nf][1] * a1;
            sel[mi * 2 + 1] += acc[mi][nf][2] * a0  + acc[mi][nf][3] * a1;
            ser[mi * 2]     += acc[mi][nf][0] * r0a + acc[mi][nf][1] * r1a;
            ser[mi * 2 + 1] += acc[mi][nf][2] * r0a + acc[mi][nf][3] * r1a;
        }
    }
    // quad reduce (lanes sharing the same row differ only in bits 0-1 of lane)
    #pragma unroll
    for (int q = 0; q < 4; q++) {
        sel[q] += __shfl_xor_sync(0xffffffffu, sel[q], 1);
        sel[q] += __shfl_xor_sync(0xffffffffu, sel[q], 2);
        ser[q] += __shfl_xor_sync(0xffffffffu, ser[q], 1);
        ser[q] += __shfl_xor_sync(0xffffffffu, ser[q], 2);
    }
    if ((lane & 3) == 0) {
        #pragma unroll
        for (int q = 0; q < 4; q++) {
            int r = rowBase + wm * 32 + (q >> 1) * 16 + (q & 1) * 8 + lr;
            if (r < M) {
                if constexpr (OUTMODE == 1) {
                    int h = colBase >> 7;  // 64-col tile lies within one head
                    atomicAdd(&g_el1[(size_t)h * NN + r], sel[q]);
                    atomicAdd(&g_er1[(size_t)r * H1 + h], ser[q]);
                } else {
                    atomicAdd(&g_el2[r], sel[q]);
                    atomicAdd(&g_er2[r], ser[q]);
                }
            }
        }
    }
}

// ---------------- launch 4: GEMM1 (needs cast) || CSR scatter (needs scan) ----------------
#define G1BLK 6256   // (F1/64) * ceil(NN/128) = 8 * 782
__global__ __launch_bounds__(256) void k_gsc(const float* __restrict__ al,
                                             const float* __restrict__ ar) {
    if (blockIdx.x < G1BLK) {
        int colBase = (blockIdx.x & 7) * 64;
        int rowBase = (blockIdx.x >> 3) * 128;
        gemm_body<D1, F1, 1>(g_xh, g_w1h, g_feat1h, NN, al, ar, rowBase, colBase);
    } else {
        int i = (blockIdx.x - G1BLK) * blockDim.x + threadIdx.x;
        if (i >= NE) return;
        int d = g_dst32[i];
        int pos = atomicAdd(&g_cursor[d], 1);
        g_ssrc[pos] = g_src32[i];
    }
}

__global__ __launch_bounds__(256) void k_gemm2h(const float* __restrict__ al,
                                                const float* __restrict__ ar) {
    gemm_body<F1, F2, 2>(g_h1h, g_w2h, g_feat2h, NN, al, ar, blockIdx.y * 128, 0);
}

// ---------------- layer1 aggregation, head-phased, branch-free 8/4/1 batches ----------------
// grid = ((NN+7)/8, H1); warp per (node, head). Head-major feat slice (25.6MB) L2-resident.
__global__ __launch_bounds__(256) void k_agg1() {
    int n = blockIdx.x * 8 + (threadIdx.x >> 5);
    int head = blockIdx.y;
    int lane = threadIdx.x & 31;
    if (n >= NN) return;
    int start = g_rowptr[n], end = g_rowptr[n + 1];
    float er_h = g_er1[n * H1 + head];
    const __half* F = g_feat1h + (size_t)head * NN * 128;
    const float* EL = g_el1 + (size_t)head * NN;
    float ax = 0.f, ay = 0.f, az = 0.f, aw = 0.f, ws = 0.f;
    int k = start;
    for (; k + 7 < end; k += 8) {
        int sl = 0; float wv = 0.f;
        if (lane < 8) {
            sl = __ldg(&g_ssrc[k + lane]);
            wv = __expf(lrelu(__ldg(&EL[sl]) + er_h));
        }
        int s0 = __shfl_sync(0xffffffffu, sl, 0);
        int s1 = __shfl_sync(0xffffffffu, sl, 1);
        int s2 = __shfl_sync(0xffffffffu, sl, 2);
        int s3 = __shfl_sync(0xffffffffu, sl, 3);
        int s4 = __shfl_sync(0xffffffffu, sl, 4);
        int s5 = __shfl_sync(0xffffffffu, sl, 5);
        int s6 = __shfl_sync(0xffffffffu, sl, 6);
        int s7 = __shfl_sync(0xffffffffu, sl, 7);
        float w0 = __shfl_sync(0xffffffffu, wv, 0);
        float w1 = __shfl_sync(0xffffffffu, wv, 1);
        float w2 = __shfl_sync(0xffffffffu, wv, 2);
        float w3 = __shfl_sync(0xffffffffu, wv, 3);
        float w4 = __shfl_sync(0xffffffffu, wv, 4);
        float w5 = __shfl_sync(0xffffffffu, wv, 5);
        float w6 = __shfl_sync(0xffffffffu, wv, 6);
        float w7 = __shfl_sync(0xffffffffu, wv, 7);
        uint2 r0 = __ldg((const uint2*)(F + (size_t)s0 * 128) + lane);
        uint2 r1 = __ldg((const uint2*)(F + (size_t)s1 * 128) + lane);
        uint2 r2 = __ldg((const uint2*)(F + (size_t)s2 * 128) + lane);
        uint2 r3 = __ldg((const uint2*)(F + (size_t)s3 * 128) + lane);
        uint2 r4 = __ldg((const uint2*)(F + (size_t)s4 * 128) + lane);
        uint2 r5 = __ldg((const uint2*)(F + (size_t)s5 * 128) + lane);
        uint2 r6 = __ldg((const uint2*)(F + (size_t)s6 * 128) + lane);
        uint2 r7 = __ldg((const uint2*)(F + (size_t)s7 * 128) + lane);
        __half2* p;
        p = (__half2*)&r0; { float2 fa = __half22float2(p[0]), fb = __half22float2(p[1]);
            ax += w0 * fa.x; ay += w0 * fa.y; az += w0 * fb.x; aw += w0 * fb.y; }
        p = (__half2*)&r1; { float2 fa = __half22float2(p[0]), fb = __half22float2(p[1]);
            ax += w1 * fa.x; ay += w1 * fa.y; az += w1 * fb.x; aw += w1 * fb.y; }
        p = (__half2*)&r2; { float2 fa = __half22float2(p[0]), fb = __half22float2(p[1]);
            ax += w2 * fa.x; ay += w2 * fa.y; az += w2 * fb.x; aw += w2 * fb.y; }
        p = (__half2*)&r3; { float2 fa = __half22float2(p[0]), fb = __half22float2(p[1]);
            ax += w3 * fa.x; ay += w3 * fa.y; az += w3 * fb.x; aw += w3 * fb.y; }
        p = (__half2*)&r4; { float2 fa = __half22float2(p[0]), fb = __half22float2(p[1]);
            ax += w4 * fa.x; ay += w4 * fa.y; az += w4 * fb.x; aw += w4 * fb.y; }
        p = (__half2*)&r5; { float2 fa = __half22float2(p[0]), fb = __half22float2(p[1]);
            ax += w5 * fa.x; ay += w5 * fa.y; az += w5 * fb.x; aw += w5 * fb.y; }
        p = (__half2*)&r6; { float2 fa = __half22float2(p[0]), fb = __half22float2(p[1]);
            ax += w6 * fa.x; ay += w6 * fa.y; az += w6 * fb.x; aw += w6 * fb.y; }
        p = (__half2*)&r7; { float2 fa = __half22float2(p[0]), fb = __half22float2(p[1]);
            ax += w7 * fa.x; ay += w7 * fa.y; az += w7 * fb.x; aw += w7 * fb.y; }
        ws += w0 + w1 + w2 + w3 + w4 + w5 + w6 + w7;
    }
    if (k + 3 < end) {
        int sl = 0; float wv = 0.f;
        if (lane < 4) {
            sl = __ldg(&g_ssrc[k + lane]);
            wv = __expf(lrelu(__ldg(&EL[sl]) + er_h));
        }
        int s0 = __shfl_sync(0xffffffffu, sl, 0);
        int s1 = __shfl_sync(0xffffffffu, sl, 1);
        int s2 = __shfl_sync(0xffffffffu, sl, 2);
        int s3 = __shfl_sync(0xffffffffu, sl, 3);
        float w0 = __shfl_sync(0xffffffffu, wv, 0);
        float w1 = __shfl_sync(0xffffffffu, wv, 1);
        float w2 = __shfl_sync(0xffffffffu, wv, 2);
        float w3 = __shfl_sync(0xffffffffu, wv, 3);
        uint2 r0 = __ldg((const uint2*)(F + (size_t)s0 * 128) + lane);
        uint2 r1 = __ldg((const uint2*)(F + (size_t)s1 * 128) + lane);
        uint2 r2 = __ldg((const uint2*)(F + (size_t)s2 * 128) + lane);
        uint2 r3 = __ldg((const uint2*)(F + (size_t)s3 * 128) + lane);
        __half2* p;
        p = (__half2*)&r0; { float2 fa = __half22float2(p[0]), fb = __half22float2(p[1]);
            ax += w0 * fa.x; ay += w0 * fa.y; az += w0 * fb.x; aw += w0 * fb.y; }
        p = (__half2*)&r1; { float2 fa = __half22float2(p[0]), fb = __half22float2(p[1]);
            ax += w1 * fa.x; ay += w1 * fa.y; az += w1 * fb.x; aw += w1 * fb.y; }
        p = (__half2*)&r2; { float2 fa = __half22float2(p[0]), fb = __half22float2(p[1]);
            ax += w2 * fa.x; ay += w2 * fa.y; az += w2 * fb.x; aw += w2 * fb.y; }
        p = (__half2*)&r3; { float2 fa = __half22float2(p[0]), fb = __half22float2(p[1]);
            ax += w3 * fa.x; ay += w3 * fa.y; az += w3 * fb.x; aw += w3 * fb.y; }
        ws += w0 + w1 + w2 + w3;
        k += 4;
    }
    for (; k < end; k++) {
        int sl = 0; float wv = 0.f;
        if (lane == 0) {
            sl = __ldg(&g_ssrc[k]);
            wv = __expf(lrelu(__ldg(&EL[sl]) + er_h));
        }
        int s0 = __shfl_sync(0xffffffffu, sl, 0);
        float w0 = __shfl_sync(0xffffffffu, wv, 0);
        uint2 r0 = __ldg((const uint2*)(F + (size_t)s0 * 128) + lane);
        __half2* p0 = (__half2*)&r0;
        float2 f0a = __half22float2(p0[0]), f0b = __half22float2(p0[1]);
        ax += w0 * f0a.x; ay += w0 * f0a.y; az += w0 * f0b.x; aw += w0 * f0b.y;
        ws += w0;
    }
    float sv = (end > start) ? (1.f / ws) : 0.f;
    ax *= sv; ay *= sv; az *= sv; aw *= sv;
    // ELU (alpha=1)
    ax = ax > 0.f ? ax : expm1f(ax);
    ay = ay > 0.f ? ay : expm1f(ay);
    az = az > 0.f ? az : expm1f(az);
    aw = aw > 0.f ? aw : expm1f(aw);
    __half2 h0 = __floats2half2_rn(ax, ay);
    __half2 h1 = __floats2half2_rn(az, aw);
    *(uint2*)(g_h1h + (size_t)n * F1 + head * 128 + lane * 4) =
        make_uint2(*(uint32_t*)&h0, *(uint32_t*)&h1);
}

// ---------------- layer2 aggregation (fp16 gather), branch-free 8/4/1 batches ----------------
__global__ __launch_bounds__(256) void k_agg2(float* __restrict__ out) {
    int n = blockIdx.x * 8 + (threadIdx.x >> 5);
    int lane = threadIdx.x & 31;
    if (n >= NN) return;
    int start = g_rowptr[n], end = g_rowptr[n + 1];
    float er_n = g_er2[n];
    float ax = 0.f, ay = 0.f, ws = 0.f;
    int k = start;
    for (; k + 7 < end; k += 8) {
        int sl = 0; float wv = 0.f;
        if (lane < 8) {
            sl = __ldg(&g_ssrc[k + lane]);
            wv = __expf(lrelu(__ldg(&g_el2[sl]) + er_n));
        }
        int s0 = __shfl_sync(0xffffffffu, sl, 0);
        int s1 = __shfl_sync(0xffffffffu, sl, 1);
        int s2 = __shfl_sync(0xffffffffu, sl, 2);
        int s3 = __shfl_sync(0xffffffffu, sl, 3);
        int s4 = __shfl_sync(0xffffffffu, sl, 4);
        int s5 = __shfl_sync(0xffffffffu, sl, 5);
        int s6 = __shfl_sync(0xffffffffu, sl, 6);
        int s7 = __shfl_sync(0xffffffffu, sl, 7);
        float w0 = __shfl_sync(0xffffffffu, wv, 0);
        float w1 = __shfl_sync(0xffffffffu, wv, 1);
        float w2 = __shfl_sync(0xffffffffu, wv, 2);
        float w3 = __shfl_sync(0xffffffffu, wv, 3);
        float w4 = __shfl_sync(0xffffffffu, wv, 4);
        float w5 = __shfl_sync(0xffffffffu, wv, 5);
        float w6 = __shfl_sync(0xffffffffu, wv, 6);
        float w7 = __shfl_sync(0xffffffffu, wv, 7);
        uint32_t r0 = __ldg((const uint32_t*)(g_feat2h + (size_t)s0 * F2) + lane);
        uint32_t r1 = __ldg((const uint32_t*)(g_feat2h + (size_t)s1 * F2) + lane);
        uint32_t r2 = __ldg((const uint32_t*)(g_feat2h + (size_t)s2 * F2) + lane);
        uint32_t r3 = __ldg((const uint32_t*)(g_feat2h + (size_t)s3 * F2) + lane);
        uint32_t r4 = __ldg((const uint32_t*)(g_feat2h + (size_t)s4 * F2) + lane);
        uint32_t r5 = __ldg((const uint32_t*)(g_feat2h + (size_t)s5 * F2) + lane);
        uint32_t r6 = __ldg((const uint32_t*)(g_feat2h + (size_t)s6 * F2) + lane);
        uint32_t r7 = __ldg((const uint32_t*)(g_feat2h + (size_t)s7 * F2) + lane);
        float2 f;
        f = __half22float2(*(__half2*)&r0); ax += w0 * f.x; ay += w0 * f.y;
        f = __half22float2(*(__half2*)&r1); ax += w1 * f.x; ay += w1 * f.y;
        f = __half22float2(*(__half2*)&r2); ax += w2 * f.x; ay += w2 * f.y;
        f = __half22float2(*(__half2*)&r3); ax += w3 * f.x; ay += w3 * f.y;
        f = __half22float2(*(__half2*)&r4); ax += w4 * f.x; ay += w4 * f.y;
        f = __half22float2(*(__half2*)&r5); ax += w5 * f.x; ay += w5 * f.y;
        f = __half22float2(*(__half2*)&r6); ax += w6 * f.x; ay += w6 * f.y;
        f = __half22float2(*(__half2*)&r7); ax += w7 * f.x; ay += w7 * f.y;
        ws += w0 + w1 + w2 + w3 + w4 + w5 + w6 + w7;
    }
    if (k + 3 < end) {
        int sl = 0; float wv = 0.f;
        if (lane < 4) {
            sl = __ldg(&g_ssrc[k + lane]);
            wv = __expf(lrelu(__ldg(&g_el2[sl]) + er_n));
        }
        int s0 = __shfl_sync(0xffffffffu, sl, 0);
        int s1 = __shfl_sync(0xffffffffu, sl, 1);
        int s2 = __shfl_sync(0xffffffffu, sl, 2);
        int s3 = __shfl_sync(0xffffffffu, sl, 3);
        float w0 = __shfl_sync(0xffffffffu, wv, 0);
        float w1 = __shfl_sync(0xffffffffu, wv, 1);
        float w2 = __shfl_sync(0xffffffffu, wv, 2);
        float w3 = __shfl_sync(0xffffffffu, wv, 3);
        uint32_t r0 = __ldg((const uint32_t*)(g_feat2h + (size_t)s0 * F2) + lane);
        uint32_t r1 = __ldg((const uint32_t*)(g_feat2h + (size_t)s1 * F2) + lane);
        uint32_t r2 = __ldg((const uint32_t*)(g_feat2h + (size_t)s2 * F2) + lane);
        uint32_t r3 = __ldg((const uint32_t*)(g_feat2h + (size_t)s3 * F2) + lane);
        float2 f;
        f = __half22float2(*(__half2*)&r0); ax += w0 * f.x; ay += w0 * f.y;
        f = __half22float2(*(__half2*)&r1); ax += w1 * f.x; ay += w1 * f.y;
        f = __half22float2(*(__half2*)&r2); ax += w2 * f.x; ay += w2 * f.y;
        f = __half22float2(*(__half2*)&r3); ax += w3 * f.x; ay += w3 * f.y;
        ws += w0 + w1 + w2 + w3;
        k += 4;
    }
    for (; k < end; k++) {
        int sl = 0; float wv = 0.f;
        if (lane == 0) {
            sl = __ldg(&g_ssrc[k]);
            wv = __expf(lrelu(__ldg(&g_el2[sl]) + er_n));
        }
        int s0 = __shfl_sync(0xffffffffu, sl, 0);
        float w0 = __shfl_sync(0xffffffffu, wv, 0);
        uint32_t r0 = __ldg((const uint32_t*)(g_feat2h + (size_t)s0 * F2) + lane);
        float2 f0 = __half22float2(*(__half2*)&r0);
        ax += w0 * f0.x; ay += w0 * f0.y;
        ws += w0;
    }
    float sv = (end > start) ? (1.f / ws) : 0.f;
    *(float2*)(out + (size_t)n * F2 + lane * 2) = make_float2(ax * sv, ay * sv);
}

// ---------------- launch ----------------
extern "C" void kernel_launch(void* const* d_in, const int* in_sizes, int n_in,
                              void* d_out, int out_size) {
    const float* x   = (const float*)d_in[0];
    const float* W1  = (const float*)d_in[1];
    const float* al1 = (const float*)d_in[2];
    const float* ar1 = (const float*)d_in[3];
    const float* W2  = (const float*)d_in[4];
    const float* al2 = (const float*)d_in[5];
    const float* ar2 = (const float*)d_in[6];
    const void*  src = d_in[7];
    const void*  dst = d_in[8];
    float* out = (float*)d_out;

    const int WB = (NN + 7) / 8;                // 12500
    const int MTILES = (NN + 127) / 128;        // 782

    // 1: detect + zero accumulators/deg
    k_setup0<<<1 + (NN * H1 + 255) / 256, 256>>>((const long long*)src);
    // 2: conv || cast (independent)
    k_setup1<<<EBLK * 2, 256>>>((const float4*)x, (const float4*)W1, (const float4*)W2,
                                src, dst);
    // 3: rowptr scan
    k_scan<<<1, 1024>>>();
    // 4 (profiled slot): GEMM1 || scatter (independent)
    k_gsc<<<G1BLK + EBLK, 256>>>(al1, ar1);
    // 5: layer1 aggregation (head-phased)
    k_agg1<<<dim3(WB, H1), 256>>>();
    // 6: GEMM2 + fused scores
    k_gemm2h<<<dim3(1, MTILES), 256>>>(al2, ar2);
    // 7: layer2 aggregation -> out
    k_agg2<<<WB, 256>>>(out);
}

// round 11
// speedup vs baseline: 1.0012x; 1.0012x over previous
#include <cuda_runtime.h>
#include <cuda_fp16.h>
#include <math.h>
#include <stdint.h>

// Problem constants (fixed by the reference)
#define NN 100000
#define NE 3200000
#define H1 4
#define D1 128
#define F1 512     // H1*D1
#define F2 64
#define NEG_SLOPE 0.2f

// ---------------- scratch (static __device__ arrays; allocation is forbidden) ----------------
__device__ __align__(16) __half g_xh[(size_t)NN * D1];      // x in fp16 (25.6 MB)
__device__ __align__(16) __half g_w1h[D1 * F1];             // W1 fp16
__device__ __align__(16) __half g_w2h[F1 * F2];             // W2 fp16
__device__ __align__(16) __half g_feat1h[(size_t)NN * F1];  // layer1 linear out, HEAD-MAJOR [H][N][128]
__device__ __align__(16) __half g_h1h[(size_t)NN * F1];     // ELU(agg1) fp16, node-major [N][512]
__device__ __align__(16) __half g_feat2h[(size_t)NN * F2];  // layer2 linear out fp16 (12.8 MB)
__device__ float g_el1[H1 * NN];           // HEAD-MAJOR [H][N]
__device__ float g_er1[NN * H1];           // node-major
__device__ float g_el2[NN],      g_er2[NN];
__device__ int g_src32[NE], g_dst32[NE];   // int32 index mirrors (coalesced scatter)
__device__ int g_ssrc[NE];                 // src id per CSR slot
__device__ int g_deg[NN];
__device__ int g_rowptr[NN + 1];
__device__ int g_cursor[NN];
__device__ int g_mode;                     // 0 = int64 indices, 1 = int32 indices

// ---------------- helpers ----------------
__device__ __forceinline__ float lrelu(float x) { return x >= 0.f ? x : NEG_SLOPE * x; }

__device__ __forceinline__ void ldsm_x4(uint32_t r[4], uint32_t addr) {
    asm volatile("ldmatrix.sync.aligned.m8n8.x4.shared.b16 {%0,%1,%2,%3}, [%4];"
                 : "=r"(r[0]), "=r"(r[1]), "=r"(r[2]), "=r"(r[3]) : "r"(addr));
}
__device__ __forceinline__ void ldsm_x4_t(uint32_t r[4], uint32_t addr) {
    asm volatile("ldmatrix.sync.aligned.m8n8.x4.trans.shared.b16 {%0,%1,%2,%3}, [%4];"
                 : "=r"(r[0]), "=r"(r[1]), "=r"(r[2]), "=r"(r[3]) : "r"(addr));
}
__device__ __forceinline__ void mma16816(float c[4], const uint32_t a[4], const uint32_t b[2]) {
    asm volatile("mma.sync.aligned.m16n8k16.row.col.f32.f16.f16.f32 "
                 "{%0,%1,%2,%3}, {%4,%5,%6,%7}, {%8,%9}, {%0,%1,%2,%3};"
                 : "+f"(c[0]), "+f"(c[1]), "+f"(c[2]), "+f"(c[3])
                 : "r"(a[0]), "r"(a[1]), "r"(a[2]), "r"(a[3]), "r"(b[0]), "r"(b[1]));
}
__device__ __forceinline__ void cp16(uint32_t smem, const void* g) {
    asm volatile("cp.async.cg.shared.global [%0], [%1], 16;" :: "r"(smem), "l"(g));
}
__device__ __forceinline__ void cp_commit() { asm volatile("cp.async.commit_group;"); }
__device__ __forceinline__ void cp_wait1() { asm volatile("cp.async.wait_group 1;"); }
__device__ __forceinline__ void cp_wait0() { asm volatile("cp.async.wait_group 0;"); }

// ---------------- launch 1: detect index width + zero deg/score accumulators ----------------
__global__ void k_setup0(const long long* __restrict__ src) {
    if (blockIdx.x == 0) {
        if (threadIdx.x == 0) {
            int m = 0;
            for (int i = 0; i < 256; i++) {
                long long v = src[i];
                if (v < 0 || v >= NN) { m = 1; break; }
            }
            g_mode = m;
        }
        return;
    }
    int i = (blockIdx.x - 1) * blockDim.x + threadIdx.x;
    if (i < NN * H1) { g_el1[i] = 0.f; g_er1[i] = 0.f; }
    if (i < NN) { g_deg[i] = 0; g_el2[i] = 0.f; g_er2[i] = 0.f; }
}

// ---------------- launch 2: conv (index widen + degree hist) || cast (fp32->fp16) ----------
__device__ __forceinline__ uint2 f4toh(float4 v) {
    __half2 a = __floats2half2_rn(v.x, v.y);
    __half2 b = __floats2half2_rn(v.z, v.w);
    uint2 r;
    r.x = *(uint32_t*)&a;
    r.y = *(uint32_t*)&b;
    return r;
}
#define EBLK 12500
__global__ void k_setup1(const float4* __restrict__ x, const float4* __restrict__ w1,
                         const float4* __restrict__ w2,
                         const void* __restrict__ srcp, const void* __restrict__ dstp) {
    if (blockIdx.x < EBLK) {
        // conv
        int i = blockIdx.x * blockDim.x + threadIdx.x;
        if (i >= NE) return;
        int s, d;
        if (g_mode) {
            s = ((const int*)srcp)[i];
            d = ((const int*)dstp)[i];
        } else {
            s = (int)((const long long*)srcp)[i];
            d = (int)((const long long*)dstp)[i];
        }
        g_src32[i] = s;
        g_dst32[i] = d;
        atomicAdd(&g_deg[d], 1);
    } else {
        // cast
        int i = (blockIdx.x - EBLK) * blockDim.x + threadIdx.x;
        if (i < NN * D1 / 4) ((uint2*)g_xh)[i]  = f4toh(x[i]);
        if (i < D1 * F1 / 4) ((uint2*)g_w1h)[i] = f4toh(w1[i]);
        if (i < F1 * F2 / 4) ((uint2*)g_w2h)[i] = f4toh(w2[i]);
    }
}

// ---------------- launch 3: parallel exclusive scan of degrees ----------------
__global__ __launch_bounds__(1024) void k_scan() {
    const int PER = (NN + 1023) / 1024;  // 98
    int tid = threadIdx.x, lane = tid & 31, wid = tid >> 5;
    int base = tid * PER;
    int sum = 0;
    for (int j = 0; j < PER; j++) {
        int i = base + j;
        if (i < NN) sum += g_deg[i];
    }
    int incl = sum;
    #pragma unroll
    for (int o = 1; o < 32; o <<= 1) {
        int t = __shfl_up_sync(0xffffffffu, incl, o);
        if (lane >= o) incl += t;
    }
    __shared__ int wsum[32];
    if (lane == 31) wsum[wid] = incl;
    __syncthreads();
    if (wid == 0) {
        int v = wsum[lane];
        int z = v;
        #pragma unroll
        for (int o = 1; o < 32; o <<= 1) {
            int t = __shfl_up_sync(0xffffffffu, z, o);
            if (lane >= o) z += t;
        }
        wsum[lane] = z - v;
    }
    __syncthreads();
    int run = incl - sum + wsum[wid];
    for (int j = 0; j < PER; j++) {
        int i = base + j;
        if (i < NN) {
            g_rowptr[i] = run;
            g_cursor[i] = run;
            run += g_deg[i];
        }
    }
    if (tid == 1023) g_rowptr[NN] = run;
}

// ---------------- HMMA fp16 GEMM, cp.async double-buffered, fused score epilogue ----------
// BM=128, BN=64, BK=32; 8 warps (4m x 2n), 32x32 per warp.
// OUTMODE 1: fp16 head-major C ([H][NN][128]); scores -> el1 (head-major), er1 (node-major)
// OUTMODE 2: fp16 node-major C ([NN][64]);      scores -> el2, er2
template<int K, int N, int OUTMODE>
__device__ __forceinline__ void gemm_body(const __half* __restrict__ A,
                                          const __half* __restrict__ B,
                                          __half* __restrict__ Ch, int M,
                                          const float* __restrict__ al,
                                          const float* __restrict__ ar,
                                          int rowBase, int colBase) {
    __shared__ __half As[2][128][40];  // +8 pad
    __shared__ __half Bs[2][32][72];   // +8 pad
    int tid = threadIdx.x;
    int lane = tid & 31, wid = tid >> 5;
    int wm = wid >> 1, wn = wid & 1;

    float acc[2][4][4];
    #pragma unroll
    for (int a = 0; a < 2; a++)
        #pragma unroll
        for (int b = 0; b < 4; b++)
            #pragma unroll
            for (int c = 0; c < 4; c++) acc[a][b][c] = 0.f;

    uint32_t as_base = (uint32_t)__cvta_generic_to_shared(&As[0][0][0]);
    uint32_t bs_base = (uint32_t)__cvta_generic_to_shared(&Bs[0][0][0]);

    auto load_tiles = [&](int kt, int b) {
        #pragma unroll
        for (int hh = 0; hh < 2; hh++) {
            int r = (tid >> 2) + hh * 64;
            int grow = rowBase + r;
            if (grow >= M) grow = M - 1;
            cp16(as_base + (uint32_t)(((b << 7) + r) * 40 + (tid & 3) * 8) * 2,
                 A + (size_t)grow * K + kt + (tid & 3) * 8);
        }
        int r = tid >> 3, c = (tid & 7) * 8;
        cp16(bs_base + (uint32_t)(((b << 5) + r) * 72 + c) * 2,
             B + (size_t)(kt + r) * N + colBase + c);
    };

    int g = lane >> 3;
    int arow_l = (lane & 7) + ((g & 1) ? 8 : 0);
    int acol_l = (g & 2) ? 8 : 0;
    int brow_l = ((g & 1) ? 8 : 0) + (lane & 7);
    int bcol_l = (g & 2) ? 8 : 0;

    const int NIT = K / 32;
    load_tiles(0, 0);
    cp_commit();
    int buf = 0;
    for (int it = 0; it < NIT; it++) {
        if (it + 1 < NIT) {
            load_tiles((it + 1) * 32, buf ^ 1);
            cp_commit();
            cp_wait1();
        } else {
            cp_wait0();
        }
        __syncthreads();
        #pragma unroll
        for (int kk = 0; kk < 2; kk++) {
            uint32_t af[2][4], bf[4][2];
            #pragma unroll
            for (int mi = 0; mi < 2; mi++) {
                int arow = wm * 32 + mi * 16 + arow_l;
                int acol = kk * 16 + acol_l;
                ldsm_x4(af[mi], as_base + (uint32_t)(((buf << 7) + arow) * 40 + acol) * 2);
            }
            #pragma unroll
            for (int n2 = 0; n2 < 2; n2++) {
                int kr = kk * 16 + brow_l;
                int nc = wn * 32 + n2 * 16 + bcol_l;
                uint32_t r4[4];
                ldsm_x4_t(r4, bs_base + (uint32_t)(((buf << 5) + kr) * 72 + nc) * 2);
                bf[n2 * 2][0] = r4[0]; bf[n2 * 2][1] = r4[1];
                bf[n2 * 2 + 1][0] = r4[2]; bf[n2 * 2 + 1][1] = r4[3];
            }
            #pragma unroll
            for (int mi = 0; mi < 2; mi++)
                #pragma unroll
                for (int nf = 0; nf < 4; nf++)
                    mma16816(acc[mi][nf], af[mi], bf[nf]);
        }
        __syncthreads();
        buf ^= 1;
    }

    int lr = lane >> 2, lc = (lane & 3) * 2;

    // ---- store C + accumulate per-row score partials ----
    float sel[4] = {0.f, 0.f, 0.f, 0.f};   // rows: wm*32 + {lr, lr+8, 16+lr, 24+lr}
    float ser[4] = {0.f, 0.f, 0.f, 0.f};
    #pragma unroll
    for (int mi = 0; mi < 2; mi++) {
        #pragma unroll
        for (int nf = 0; nf < 4; nf++) {
            int r0 = rowBase + wm * 32 + mi * 16 + lr;
            int cc = colBase + wn * 32 + nf * 8 + lc;
            float a0, a1, r0a, r1a;
            if constexpr (OUTMODE == 1) {
                int h = cc >> 7, d = cc & 127;
                a0 = __ldg(&al[h * 128 + d]);     a1 = __ldg(&al[h * 128 + d + 1]);
                r0a = __ldg(&ar[h * 128 + d]);    r1a = __ldg(&ar[h * 128 + d + 1]);
                if (r0 < M)
                    *(__half2*)(Ch + ((size_t)h * NN + r0) * 128 + d) =
                        __floats2half2_rn(acc[mi][nf][0], acc[mi][nf][1]);
                if (r0 + 8 < M)
                    *(__half2*)(Ch + ((size_t)h * NN + r0 + 8) * 128 + d) =
                        __floats2half2_rn(acc[mi][nf][2], acc[mi][nf][3]);
            } else {
                a0 = __ldg(&al[cc]);  a1 = __ldg(&al[cc + 1]);
                r0a = __ldg(&ar[cc]); r1a = __ldg(&ar[cc + 1]);
                if (r0 < M)
                    *(__half2*)(Ch + (size_t)r0 * N + cc) =
                        __floats2half2_rn(acc[mi][nf][0], acc[mi][nf][1]);
                if (r0 + 8 < M)
                    *(__half2*)(Ch + (size_t)(r0 + 8) * N + cc) =
                        __floats2half2_rn(acc[mi][nf][2], acc[mi][nf][3]);
            }
            sel[mi * 2]     += acc[mi][nf][0] * a0  + acc[mi][nf][1] * a1;
            sel[mi * 2 + 1] += acc[mi][nf][2] * a0  + acc[mi][nf][3] * a1;
            ser[mi * 2]     += acc[mi][nf][0] * r0a + acc[mi][nf][1] * r1a;
            ser[mi * 2 + 1] += acc[mi][nf][2] * r0a + acc[mi][nf][3] * r1a;
        }
    }
    // quad reduce (lanes sharing the same row differ only in bits 0-1 of lane)
    #pragma unroll
    for (int q = 0; q < 4; q++) {
        sel[q] += __shfl_xor_sync(0xffffffffu, sel[q], 1);
        sel[q] += __shfl_xor_sync(0xffffffffu, sel[q], 2);
        ser[q] += __shfl_xor_sync(0xffffffffu, ser[q], 1);
        ser[q] += __shfl_xor_sync(0xffffffffu, ser[q], 2);
    }
    if ((lane & 3) == 0) {
        #pragma unroll
        for (int q = 0; q < 4; q++) {
            int r = rowBase + wm * 32 + (q >> 1) * 16 + (q & 1) * 8 + lr;
            if (r < M) {
                if constexpr (OUTMODE == 1) {
                    int h = colBase >> 7;  // 64-col tile lies within one head
                    atomicAdd(&g_el1[(size_t)h * NN + r], sel[q]);
                    atomicAdd(&g_er1[(size_t)r * H1 + h], ser[q]);
                } else {
                    atomicAdd(&g_el2[r], sel[q]);
                    atomicAdd(&g_er2[r], ser[q]);
                }
            }
        }
    }
}

// ---------------- launch 4: GEMM1 (needs cast) || CSR scatter (needs scan) ----------------
#define G1BLK 6256   // (F1/64) * ceil(NN/128) = 8 * 782
__global__ __launch_bounds__(256) void k_gsc(const float* __restrict__ al,
                                             const float* __restrict__ ar) {
    if (blockIdx.x < G1BLK) {
        int colBase = (blockIdx.x & 7) * 64;
        int rowBase = (blockIdx.x >> 3) * 128;
        gemm_body<D1, F1, 1>(g_xh, g_w1h, g_feat1h, NN, al, ar, rowBase, colBase);
    } else {
        int i = (blockIdx.x - G1BLK) * blockDim.x + threadIdx.x;
        if (i >= NE) return;
        int d = g_dst32[i];
        int pos = atomicAdd(&g_cursor[d], 1);
        g_ssrc[pos] = g_src32[i];
    }
}

__global__ __launch_bounds__(256) void k_gemm2h(const float* __restrict__ al,
                                                const float* __restrict__ ar) {
    gemm_body<F1, F2, 2>(g_h1h, g_w2h, g_feat2h, NN, al, ar, blockIdx.y * 128, 0);
}

// ---------------- layer1 aggregation, head-phased, branch-free 8/4/1 batches ----------------
// grid = ((NN+7)/8, H1); warp per (node, head). Head-major feat slice (25.6MB) L2-resident.
__global__ __launch_bounds__(256) void k_agg1() {
    int n = blockIdx.x * 8 + (threadIdx.x >> 5);
    int head = blockIdx.y;
    int lane = threadIdx.x & 31;
    if (n >= NN) return;
    int start = g_rowptr[n], end = g_rowptr[n + 1];
    float er_h = g_er1[n * H1 + head];
    const __half* F = g_feat1h + (size_t)head * NN * 128;
    const float* EL = g_el1 + (size_t)head * NN;
    float ax = 0.f, ay = 0.f, az = 0.f, aw = 0.f, ws = 0.f;
    int k = start;
    for (; k + 7 < end; k += 8) {
        int sl = 0; float wv = 0.f;
        if (lane < 8) {
            sl = __ldg(&g_ssrc[k + lane]);
            wv = __expf(lrelu(__ldg(&EL[sl]) + er_h));
        }
        int s0 = __shfl_sync(0xffffffffu, sl, 0);
        int s1 = __shfl_sync(0xffffffffu, sl, 1);
        int s2 = __shfl_sync(0xffffffffu, sl, 2);
        int s3 = __shfl_sync(0xffffffffu, sl, 3);
        int s4 = __shfl_sync(0xffffffffu, sl, 4);
        int s5 = __shfl_sync(0xffffffffu, sl, 5);
        int s6 = __shfl_sync(0xffffffffu, sl, 6);
        int s7 = __shfl_sync(0xffffffffu, sl, 7);
        float w0 = __shfl_sync(0xffffffffu, wv, 0);
        float w1 = __shfl_sync(0xffffffffu, wv, 1);
        float w2 = __shfl_sync(0xffffffffu, wv, 2);
        float w3 = __shfl_sync(0xffffffffu, wv, 3);
        float w4 = __shfl_sync(0xffffffffu, wv, 4);
        float w5 = __shfl_sync(0xffffffffu, wv, 5);
        float w6 = __shfl_sync(0xffffffffu, wv, 6);
        float w7 = __shfl_sync(0xffffffffu, wv, 7);
        uint2 r0 = __ldg((const uint2*)(F + (size_t)s0 * 128) + lane);
        uint2 r1 = __ldg((const uint2*)(F + (size_t)s1 * 128) + lane);
        uint2 r2 = __ldg((const uint2*)(F + (size_t)s2 * 128) + lane);
        uint2 r3 = __ldg((const uint2*)(F + (size_t)s3 * 128) + lane);
        uint2 r4 = __ldg((const uint2*)(F + (size_t)s4 * 128) + lane);
        uint2 r5 = __ldg((const uint2*)(F + (size_t)s5 * 128) + lane);
        uint2 r6 = __ldg((const uint2*)(F + (size_t)s6 * 128) + lane);
        uint2 r7 = __ldg((const uint2*)(F + (size_t)s7 * 128) + lane);
        __half2* p;
        p = (__half2*)&r0; { float2 fa = __half22float2(p[0]), fb = __half22float2(p[1]);
            ax += w0 * fa.x; ay += w0 * fa.y; az += w0 * fb.x; aw += w0 * fb.y; }
        p = (__half2*)&r1; { float2 fa = __half22float2(p[0]), fb = __half22float2(p[1]);
            ax += w1 * fa.x; ay += w1 * fa.y; az += w1 * fb.x; aw += w1 * fb.y; }
        p = (__half2*)&r2; { float2 fa = __half22float2(p[0]), fb = __half22float2(p[1]);
            ax += w2 * fa.x; ay += w2 * fa.y; az += w2 * fb.x; aw += w2 * fb.y; }
        p = (__half2*)&r3; { float2 fa = __half22float2(p[0]), fb = __half22float2(p[1]);
            ax += w3 * fa.x; ay += w3 * fa.y; az += w3 * fb.x; aw += w3 * fb.y; }
        p = (__half2*)&r4; { float2 fa = __half22float2(p[0]), fb = __half22float2(p[1]);
            ax += w4 * fa.x; ay += w4 * fa.y; az += w4 * fb.x; aw += w4 * fb.y; }
        p = (__half2*)&r5; { float2 fa = __half22float2(p[0]), fb = __half22float2(p[1]);
            ax += w5 * fa.x; ay += w5 * fa.y; az += w5 * fb.x; aw += w5 * fb.y; }
        p = (__half2*)&r6; { float2 fa = __half22float2(p[0]), fb = __half22float2(p[1]);
            ax += w6 * fa.x; ay += w6 * fa.y; az += w6 * fb.x; aw += w6 * fb.y; }
        p = (__half2*)&r7; { float2 fa = __half22float2(p[0]), fb = __half22float2(p[1]);
            ax += w7 * fa.x; ay += w7 * fa.y; az += w7 * fb.x; aw += w7 * fb.y; }
        ws += w0 + w1 + w2 + w3 + w4 + w5 + w6 + w7;
    }
    if (k + 3 < end) {
        int sl = 0; float wv = 0.f;
        if (lane < 4) {
            sl = __ldg(&g_ssrc[k + lane]);
            wv = __expf(lrelu(__ldg(&EL[sl]) + er_h));
        }
        int s0 = __shfl_sync(0xffffffffu, sl, 0);
        int s1 = __shfl_sync(0xffffffffu, sl, 1);
        int s2 = __shfl_sync(0xffffffffu, sl, 2);
        int s3 = __shfl_sync(0xffffffffu, sl, 3);
        float w0 = __shfl_sync(0xffffffffu, wv, 0);
        float w1 = __shfl_sync(0xffffffffu, wv, 1);
        float w2 = __shfl_sync(0xffffffffu, wv, 2);
        float w3 = __shfl_sync(0xffffffffu, wv, 3);
        uint2 r0 = __ldg((const uint2*)(F + (size_t)s0 * 128) + lane);
        uint2 r1 = __ldg((const uint2*)(F + (size_t)s1 * 128) + lane);
        uint2 r2 = __ldg((const uint2*)(F + (size_t)s2 * 128) + lane);
        uint2 r3 = __ldg((const uint2*)(F + (size_t)s3 * 128) + lane);
        __half2* p;
        p = (__half2*)&r0; { float2 fa = __half22float2(p[0]), fb = __half22float2(p[1]);
            ax += w0 * fa.x; ay += w0 * fa.y; az += w0 * fb.x; aw += w0 * fb.y; }
        p = (__half2*)&r1; { float2 fa = __half22float2(p[0]), fb = __half22float2(p[1]);
            ax += w1 * fa.x; ay += w1 * fa.y; az += w1 * fb.x; aw += w1 * fb.y; }
        p = (__half2*)&r2; { float2 fa = __half22float2(p[0]), fb = __half22float2(p[1]);
            ax += w2 * fa.x; ay += w2 * fa.y; az += w2 * fb.x; aw += w2 * fb.y; }
        p = (__half2*)&r3; { float2 fa = __half22float2(p[0]), fb = __half22float2(p[1]);
            ax += w3 * fa.x; ay += w3 * fa.y; az += w3 * fb.x; aw += w3 * fb.y; }
        ws += w0 + w1 + w2 + w3;
        k += 4;
    }
    for (; k < end; k++) {
        int sl = 0; float wv = 0.f;
        if (lane == 0) {
            sl = __ldg(&g_ssrc[k]);
            wv = __expf(lrelu(__ldg(&EL[sl]) + er_h));
        }
        int s0 = __shfl_sync(0xffffffffu, sl, 0);
        float w0 = __shfl_sync(0xffffffffu, wv, 0);
        uint2 r0 = __ldg((const uint2*)(F + (size_t)s0 * 128) + lane);
        __half2* p0 = (__half2*)&r0;
        float2 f0a = __half22float2(p0[0]), f0b = __half22float2(p0[1]);
        ax += w0 * f0a.x; ay += w0 * f0a.y; az += w0 * f0b.x; aw += w0 * f0b.y;
        ws += w0;
    }
    float sv = (end > start) ? (1.f / ws) : 0.f;
    ax *= sv; ay *= sv; az *= sv; aw *= sv;
    // ELU (alpha=1)
    ax = ax > 0.f ? ax : expm1f(ax);
    ay = ay > 0.f ? ay : expm1f(ay);
    az = az > 0.f ? az : expm1f(az);
    aw = aw > 0.f ? aw : expm1f(aw);
    __half2 h0 = __floats2half2_rn(ax, ay);
    __half2 h1 = __floats2half2_rn(az, aw);
    *(uint2*)(g_h1h + (size_t)n * F1 + head * 128 + lane * 4) =
        make_uint2(*(uint32_t*)&h0, *(uint32_t*)&h1);
}

// ---------------- layer2 aggregation (fp16 gather), branch-free 8/4/1 batches ----------------
__global__ __launch_bounds__(256) void k_agg2(float* __restrict__ out) {
    int n = blockIdx.x * 8 + (threadIdx.x >> 5);
    int lane = threadIdx.x & 31;
    if (n >= NN) return;
    int start = g_rowptr[n], end = g_rowptr[n + 1];
    float er_n = g_er2[n];
    float ax = 0.f, ay = 0.f, ws = 0.f;
    int k = start;
    for (; k + 7 < end; k += 8) {
        int sl = 0; float wv = 0.f;
        if (lane < 8) {
            sl = __ldg(&g_ssrc[k + lane]);
            wv = __expf(lrelu(__ldg(&g_el2[sl]) + er_n));
        }
        int s0 = __shfl_sync(0xffffffffu, sl, 0);
        int s1 = __shfl_sync(0xffffffffu, sl, 1);
        int s2 = __shfl_sync(0xffffffffu, sl, 2);
        int s3 = __shfl_sync(0xffffffffu, sl, 3);
        int s4 = __shfl_sync(0xffffffffu, sl, 4);
        int s5 = __shfl_sync(0xffffffffu, sl, 5);
        int s6 = __shfl_sync(0xffffffffu, sl, 6);
        int s7 = __shfl_sync(0xffffffffu, sl, 7);
        float w0 = __shfl_sync(0xffffffffu, wv, 0);
        float w1 = __shfl_sync(0xffffffffu, wv, 1);
        float w2 = __shfl_sync(0xffffffffu, wv, 2);
        float w3 = __shfl_sync(0xffffffffu, wv, 3);
        float w4 = __shfl_sync(0xffffffffu, wv, 4);
        float w5 = __shfl_sync(0xffffffffu, wv, 5);
        float w6 = __shfl_sync(0xffffffffu, wv, 6);
        float w7 = __shfl_sync(0xffffffffu, wv, 7);
        uint32_t r0 = __ldg((const uint32_t*)(g_feat2h + (size_t)s0 * F2) + lane);
        uint32_t r1 = __ldg((const uint32_t*)(g_feat2h + (size_t)s1 * F2) + lane);
        uint32_t r2 = __ldg((const uint32_t*)(g_feat2h + (size_t)s2 * F2) + lane);
        uint32_t r3 = __ldg((const uint32_t*)(g_feat2h + (size_t)s3 * F2) + lane);
        uint32_t r4 = __ldg((const uint32_t*)(g_feat2h + (size_t)s4 * F2) + lane);
        uint32_t r5 = __ldg((const uint32_t*)(g_feat2h + (size_t)s5 * F2) + lane);
        uint32_t r6 = __ldg((const uint32_t*)(g_feat2h + (size_t)s6 * F2) + lane);
        uint32_t r7 = __ldg((const uint32_t*)(g_feat2h + (size_t)s7 * F2) + lane);
        float2 f;
        f = __half22float2(*(__half2*)&r0); ax += w0 * f.x; ay += w0 * f.y;
        f = __half22float2(*(__half2*)&r1); ax += w1 * f.x; ay += w1 * f.y;
        f = __half22float2(*(__half2*)&r2); ax += w2 * f.x; ay += w2 * f.y;
        f = __half22float2(*(__half2*)&r3); ax += w3 * f.x; ay += w3 * f.y;
        f = __half22float2(*(__half2*)&r4); ax += w4 * f.x; ay += w4 * f.y;
        f = __half22float2(*(__half2*)&r5); ax += w5 * f.x; ay += w5 * f.y;
        f = __half22float2(*(__half2*)&r6); ax += w6 * f.x; ay += w6 * f.y;
        f = __half22float2(*(__half2*)&r7); ax += w7 * f.x; ay += w7 * f.y;
        ws += w0 + w1 + w2 + w3 + w4 + w5 + w6 + w7;
    }
    if (k + 3 < end) {
        int sl = 0; float wv = 0.f;
        if (lane < 4) {
            sl = __ldg(&g_ssrc[k + lane]);
            wv = __expf(lrelu(__ldg(&g_el2[sl]) + er_n));
        }
        int s0 = __shfl_sync(0xffffffffu, sl, 0);
        int s1 = __shfl_sync(0xffffffffu, sl, 1);
        int s2 = __shfl_sync(0xffffffffu, sl, 2);
        int s3 = __shfl_sync(0xffffffffu, sl, 3);
        float w0 = __shfl_sync(0xffffffffu, wv, 0);
        float w1 = __shfl_sync(0xffffffffu, wv, 1);
        float w2 = __shfl_sync(0xffffffffu, wv, 2);
        float w3 = __shfl_sync(0xffffffffu, wv, 3);
        uint32_t r0 = __ldg((const uint32_t*)(g_feat2h + (size_t)s0 * F2) + lane);
        uint32_t r1 = __ldg((const uint32_t*)(g_feat2h + (size_t)s1 * F2) + lane);
        uint32_t r2 = __ldg((const uint32_t*)(g_feat2h + (size_t)s2 * F2) + lane);
        uint32_t r3 = __ldg((const uint32_t*)(g_feat2h + (size_t)s3 * F2) + lane);
        float2 f;
        f = __half22float2(*(__half2*)&r0); ax += w0 * f.x; ay += w0 * f.y;
        f = __half22float2(*(__half2*)&r1); ax += w1 * f.x; ay += w1 * f.y;
        f = __half22float2(*(__half2*)&r2); ax += w2 * f.x; ay += w2 * f.y;
        f = __half22float2(*(__half2*)&r3); ax += w3 * f.x; ay += w3 * f.y;
        ws += w0 + w1 + w2 + w3;
        k += 4;
    }
    for (; k < end; k++) {
        int sl = 0; float wv = 0.f;
        if (lane == 0) {
            sl = __ldg(&g_ssrc[k]);
            wv = __expf(lrelu(__ldg(&g_el2[sl]) + er_n));
        }
        int s0 = __shfl_sync(0xffffffffu, sl, 0);
        float w0 = __shfl_sync(0xffffffffu, wv, 0);
        uint32_t r0 = __ldg((const uint32_t*)(g_feat2h + (size_t)s0 * F2) + lane);
        float2 f0 = __half22float2(*(__half2*)&r0);
        ax += w0 * f0.x; ay += w0 * f0.y;
        ws += w0;
    }
    float sv = (end > start) ? (1.f / ws) : 0.f;
    *(float2*)(out + (size_t)n * F2 + lane * 2) = make_float2(ax * sv, ay * sv);
}

// ---------------- launch ----------------
extern "C" void kernel_launch(void* const* d_in, const int* in_sizes, int n_in,
                              void* d_out, int out_size) {
    const float* x   = (const float*)d_in[0];
    const float* W1  = (const float*)d_in[1];
    const float* al1 = (const float*)d_in[2];
    const float* ar1 = (const float*)d_in[3];
    const float* W2  = (const float*)d_in[4];
    const float* al2 = (const float*)d_in[5];
    const float* ar2 = (const float*)d_in[6];
    const void*  src = d_in[7];
    const void*  dst = d_in[8];
    float* out = (float*)d_out;

    const int WB = (NN + 7) / 8;                // 12500
    const int MTILES = (NN + 127) / 128;        // 782

    // 1: detect + zero accumulators/deg
    k_setup0<<<1 + (NN * H1 + 255) / 256, 256>>>((const long long*)src);
    // 2: conv || cast (independent)
    k_setup1<<<EBLK * 2, 256>>>((const float4*)x, (const float4*)W1, (const float4*)W2,
                                src, dst);
    // 3: rowptr scan
    k_scan<<<1, 1024>>>();
    // 4 (profiled slot): GEMM1 || scatter (independent)
    k_gsc<<<G1BLK + EBLK, 256>>>(al1, ar1);
    // 5: layer1 aggregation (head-phased)
    k_agg1<<<dim3(WB, H1), 256>>>();
    // 6: GEMM2 + fused scores
    k_gemm2h<<<dim3(1, MTILES), 256>>>(al2, ar2);
    // 7: layer2 aggregation -> out
    k_agg2<<<WB, 256>>>(out);
}

// round 12
// speedup vs baseline: 1.1255x; 1.1242x over previous
#include <cuda_runtime.h>
#include <cuda_fp16.h>
#include <math.h>
#include <stdint.h>

// Problem constants (fixed by the reference)
#define NN 100000
#define NE 3200000
#define H1 4
#define D1 128
#define F1 512     // H1*D1
#define F2 64
#define NEG_SLOPE 0.2f

// ---------------- scratch (static __device__ arrays; allocation is forbidden) ----------------
__device__ __align__(16) __half g_xh[(size_t)NN * D1];      // x in fp16 (25.6 MB, L2-resident gather table)
__device__ __align__(16) __half g_w1h[D1 * F1];             // W1 fp16
__device__ __align__(16) __half g_w2h[F1 * F2];             // W2 fp16
__device__ __align__(16) __half g_aggx[(size_t)NN * F1];    // (Σ w·x)/S per (node,head): [N][H*128] fp16
__device__ __align__(16) __half g_h1h[(size_t)NN * F1];     // ELU(aggx@W1) fp16, node-major [N][512]
__device__ __align__(16) __half g_feat2h[(size_t)NN * F2];  // layer2 linear out fp16 (12.8 MB)
__device__ __align__(16) float g_vl[F1], g_vr[F1];          // W1_h @ al_h / ar_h, [h*128+i]
__device__ __align__(16) float4 g_els[NN];                  // el1 per node, 4 heads
__device__ __align__(16) float4 g_ers[NN];                  // er1 per node, 4 heads
__device__ float g_el2[NN], g_er2[NN];
__device__ int g_src32[NE], g_dst32[NE];   // int32 index mirrors
__device__ int g_ssrc[NE];                 // src id per CSR slot
__device__ int g_deg[NN];
__device__ int g_rowptr[NN + 1];
__device__ int g_cursor[NN];
__device__ int g_mode;                     // 0 = int64 indices, 1 = int32 indices

// ---------------- helpers ----------------
__device__ __forceinline__ float lrelu(float x) { return x >= 0.f ? x : NEG_SLOPE * x; }

__device__ __forceinline__ void ldsm_x4(uint32_t r[4], uint32_t addr) {
    asm volatile("ldmatrix.sync.aligned.m8n8.x4.shared.b16 {%0,%1,%2,%3}, [%4];"
                 : "=r"(r[0]), "=r"(r[1]), "=r"(r[2]), "=r"(r[3]) : "r"(addr));
}
__device__ __forceinline__ void ldsm_x4_t(uint32_t r[4], uint32_t addr) {
    asm volatile("ldmatrix.sync.aligned.m8n8.x4.trans.shared.b16 {%0,%1,%2,%3}, [%4];"
                 : "=r"(r[0]), "=r"(r[1]), "=r"(r[2]), "=r"(r[3]) : "r"(addr));
}
__device__ __forceinline__ void mma16816(float c[4], const uint32_t a[4], const uint32_t b[2]) {
    asm volatile("mma.sync.aligned.m16n8k16.row.col.f32.f16.f16.f32 "
                 "{%0,%1,%2,%3}, {%4,%5,%6,%7}, {%8,%9}, {%0,%1,%2,%3};"
                 : "+f"(c[0]), "+f"(c[1]), "+f"(c[2]), "+f"(c[3])
                 : "r"(a[0]), "r"(a[1]), "r"(a[2]), "r"(a[3]), "r"(b[0]), "r"(b[1]));
}
__device__ __forceinline__ void cp16(uint32_t smem, const void* g) {
    asm volatile("cp.async.cg.shared.global [%0], [%1], 16;" :: "r"(smem), "l"(g));
}
__device__ __forceinline__ void cp_commit() { asm volatile("cp.async.commit_group;"); }
__device__ __forceinline__ void cp_wait1() { asm volatile("cp.async.wait_group 1;"); }
__device__ __forceinline__ void cp_wait0() { asm volatile("cp.async.wait_group 0;"); }

// ---------------- launch 1: detect index width + zero deg / layer2 score accumulators ------
__global__ void k_setup0(const long long* __restrict__ src) {
    if (blockIdx.x == 0) {
        if (threadIdx.x == 0) {
            int m = 0;
            for (int i = 0; i < 256; i++) {
                long long v = src[i];
                if (v < 0 || v >= NN) { m = 1; break; }
            }
            g_mode = m;
        }
        return;
    }
    int i = (blockIdx.x - 1) * blockDim.x + threadIdx.x;
    if (i < NN) { g_deg[i] = 0; g_el2[i] = 0.f; g_er2[i] = 0.f; }
}

// ---------------- launch 2: conv || cast || score-vector precompute ----------------
__device__ __forceinline__ uint2 f4toh(float4 v) {
    __half2 a = __floats2half2_rn(v.x, v.y);
    __half2 b = __floats2half2_rn(v.z, v.w);
    uint2 r;
    r.x = *(uint32_t*)&a;
    r.y = *(uint32_t*)&b;
    return r;
}
#define EBLK 12500
__global__ void k_setup1(const float4* __restrict__ x, const float4* __restrict__ w1,
                         const float4* __restrict__ w2,
                         const void* __restrict__ srcp, const void* __restrict__ dstp,
                         const float* __restrict__ al1, const float* __restrict__ ar1) {
    if (blockIdx.x < EBLK) {
        // conv: widen indices + degree histogram
        int i = blockIdx.x * blockDim.x + threadIdx.x;
        if (i >= NE) return;
        int s, d;
        if (g_mode) {
            s = ((const int*)srcp)[i];
            d = ((const int*)dstp)[i];
        } else {
            s = (int)((const long long*)srcp)[i];
            d = (int)((const long long*)dstp)[i];
        }
        g_src32[i] = s;
        g_dst32[i] = d;
        atomicAdd(&g_deg[d], 1);
    } else if (blockIdx.x < 2 * EBLK) {
        // cast x, W1, W2 to fp16
        int i = (blockIdx.x - EBLK) * blockDim.x + threadIdx.x;
        if (i < NN * D1 / 4) ((uint2*)g_xh)[i]  = f4toh(x[i]);
        if (i < D1 * F1 / 4) ((uint2*)g_w1h)[i] = f4toh(w1[i]);
        if (i < F1 * F2 / 4) ((uint2*)g_w2h)[i] = f4toh(w2[i]);
    } else {
        // v-vectors: block b in [0,8): h = b&3, r-side = b>>2
        int b = blockIdx.x - 2 * EBLK;      // 0..7
        int h = b & 3;
        const float* W1f = (const float*)w1;
        const float* a = (b >> 2) ? ar1 : al1;
        float* v = (b >> 2) ? g_vr : g_vl;
        int i = threadIdx.x;                // 0..255, need 0..127
        if (i < 128) {
            float sum = 0.f;
            #pragma unroll 4
            for (int d = 0; d < 128; d++)
                sum += W1f[i * F1 + h * 128 + d] * a[h * 128 + d];
            v[h * 128 + i] = sum;
        }
    }
}

// ---------------- launch 3: parallel exclusive scan of degrees ----------------
__global__ __launch_bounds__(1024) void k_scan() {
    const int PER = (NN + 1023) / 1024;  // 98
    int tid = threadIdx.x, lane = tid & 31, wid = tid >> 5;
    int base = tid * PER;
    int sum = 0;
    for (int j = 0; j < PER; j++) {
        int i = base + j;
        if (i < NN) sum += g_deg[i];
    }
    int incl = sum;
    #pragma unroll
    for (int o = 1; o < 32; o <<= 1) {
        int t = __shfl_up_sync(0xffffffffu, incl, o);
        if (lane >= o) incl += t;
    }
    __shared__ int wsum[32];
    if (lane == 31) wsum[wid] = incl;
    __syncthreads();
    if (wid == 0) {
        int v = wsum[lane];
        int z = v;
        #pragma unroll
        for (int o = 1; o < 32; o <<= 1) {
            int t = __shfl_up_sync(0xffffffffu, z, o);
            if (lane >= o) z += t;
        }
        wsum[lane] = z - v;
    }
    __syncthreads();
    int run = incl - sum + wsum[wid];
    for (int j = 0; j < PER; j++) {
        int i = base + j;
        if (i < NN) {
            g_rowptr[i] = run;
            g_cursor[i] = run;
            run += g_deg[i];
        }
    }
    if (tid == 1023) g_rowptr[NN] = run;
}

// ---------------- launch 4 (profiled): CSR scatter ----------------
__global__ void k_scatter() {
    int i = blockIdx.x * blockDim.x + threadIdx.x;
    if (i >= NE) return;
    int d = g_dst32[i];
    int pos = atomicAdd(&g_cursor[d], 1);
    g_ssrc[pos] = g_src32[i];
}

// ---------------- launch 5: layer1 scores via precomputed v-vectors ----------------
// el[n,h] = x[n]·vl[h];  er[n,h] = x[n]·vr[h].  Warp per node.
__global__ __launch_bounds__(256) void k_score1() {
    int w = (blockIdx.x * blockDim.x + threadIdx.x) >> 5;
    int lane = threadIdx.x & 31;
    if (w >= NN) return;
    uint2 xv = __ldg((const uint2*)(g_xh + (size_t)w * D1) + lane);
    __half2* p = (__half2*)&xv;
    float2 xa = __half22float2(p[0]);
    float2 xb = __half22float2(p[1]);
    float el[4], er[4];
    #pragma unroll
    for (int h = 0; h < 4; h++) {
        float4 vl = *(const float4*)&g_vl[h * 128 + lane * 4];
        float4 vr = *(const float4*)&g_vr[h * 128 + lane * 4];
        el[h] = xa.x * vl.x + xa.y * vl.y + xb.x * vl.z + xb.y * vl.w;
        er[h] = xa.x * vr.x + xa.y * vr.y + xb.x * vr.z + xb.y * vr.w;
    }
    #pragma unroll
    for (int o = 16; o > 0; o >>= 1) {
        #pragma unroll
        for (int h = 0; h < 4; h++) {
            el[h] += __shfl_xor_sync(0xffffffffu, el[h], o);
            er[h] += __shfl_xor_sync(0xffffffffu, er[h], o);
        }
    }
    if (lane == 0) {
        g_els[w] = make_float4(el[0], el[1], el[2], el[3]);
        g_ers[w] = make_float4(er[0], er[1], er[2], er[3]);
    }
}

// ---------------- launch 6: aggregate x with per-head softmax weights ----------------
// Warp per node. Per edge: ONE 256B x-row gather shared by all 4 heads (was 4x before).
// Output: g_aggx[n][h*128+d] = (Σ w_h·x)/Σw_h, fp16.
__global__ __launch_bounds__(256) void k_aggx() {
    int n = blockIdx.x * 8 + (threadIdx.x >> 5);
    int lane = threadIdx.x & 31;
    if (n >= NN) return;
    int start = g_rowptr[n], end = g_rowptr[n + 1];
    float4 er4 = g_ers[n];
    float4 ac0 = {0,0,0,0}, ac1 = {0,0,0,0}, ac2 = {0,0,0,0}, ac3 = {0,0,0,0};
    float ws0 = 0.f, ws1 = 0.f, ws2 = 0.f, ws3 = 0.f;
    int k = start;
    for (; k + 3 < end; k += 4) {
        int sl = 0;
        float4 wv = {0,0,0,0};
        if (lane < 4) {
            sl = __ldg(&g_ssrc[k + lane]);
            float4 e = __ldg(&g_els[sl]);
            wv.x = __expf(lrelu(e.x + er4.x));
            wv.y = __expf(lrelu(e.y + er4.y));
            wv.z = __expf(lrelu(e.z + er4.z));
            wv.w = __expf(lrelu(e.w + er4.w));
        }
        int s0 = __shfl_sync(0xffffffffu, sl, 0);
        int s1 = __shfl_sync(0xffffffffu, sl, 1);
        int s2 = __shfl_sync(0xffffffffu, sl, 2);
        int s3 = __shfl_sync(0xffffffffu, sl, 3);
        uint2 r0 = __ldg((const uint2*)(g_xh + (size_t)s0 * D1) + lane);
        uint2 r1 = __ldg((const uint2*)(g_xh + (size_t)s1 * D1) + lane);
        uint2 r2 = __ldg((const uint2*)(g_xh + (size_t)s2 * D1) + lane);
        uint2 r3 = __ldg((const uint2*)(g_xh + (size_t)s3 * D1) + lane);
        #pragma unroll
        for (int j = 0; j < 4; j++) {
            float wx = __shfl_sync(0xffffffffu, wv.x, j);
            float wy = __shfl_sync(0xffffffffu, wv.y, j);
            float wz = __shfl_sync(0xffffffffu, wv.z, j);
            float ww = __shfl_sync(0xffffffffu, wv.w, j);
            uint2 rr = (j == 0) ? r0 : (j == 1) ? r1 : (j == 2) ? r2 : r3;
            __half2* pp = (__half2*)&rr;
            float2 fa = __half22float2(pp[0]);
            float2 fb = __half22float2(pp[1]);
            ac0.x += wx * fa.x; ac0.y += wx * fa.y; ac0.z += wx * fb.x; ac0.w += wx * fb.y;
            ac1.x += wy * fa.x; ac1.y += wy * fa.y; ac1.z += wy * fb.x; ac1.w += wy * fb.y;
            ac2.x += wz * fa.x; ac2.y += wz * fa.y; ac2.z += wz * fb.x; ac2.w += wz * fb.y;
            ac3.x += ww * fa.x; ac3.y += ww * fa.y; ac3.z += ww * fb.x; ac3.w += ww * fb.y;
            ws0 += wx; ws1 += wy; ws2 += wz; ws3 += ww;
        }
    }
    for (; k < end; k++) {
        int sl = 0;
        float4 wv = {0,0,0,0};
        if (lane == 0) {
            sl = __ldg(&g_ssrc[k]);
            float4 e = __ldg(&g_els[sl]);
            wv.x = __expf(lrelu(e.x + er4.x));
            wv.y = __expf(lrelu(e.y + er4.y));
            wv.z = __expf(lrelu(e.z + er4.z));
            wv.w = __expf(lrelu(e.w + er4.w));
        }
        int s0 = __shfl_sync(0xffffffffu, sl, 0);
        float wx = __shfl_sync(0xffffffffu, wv.x, 0);
        float wy = __shfl_sync(0xffffffffu, wv.y, 0);
        float wz = __shfl_sync(0xffffffffu, wv.z, 0);
        float ww = __shfl_sync(0xffffffffu, wv.w, 0);
        uint2 rr = __ldg((const uint2*)(g_xh + (size_t)s0 * D1) + lane);
        __half2* pp = (__half2*)&rr;
        float2 fa = __half22float2(pp[0]);
        float2 fb = __half22float2(pp[1]);
        ac0.x += wx * fa.x; ac0.y += wx * fa.y; ac0.z += wx * fb.x; ac0.w += wx * fb.y;
        ac1.x += wy * fa.x; ac1.y += wy * fa.y; ac1.z += wy * fb.x; ac1.w += wy * fb.y;
        ac2.x += wz * fa.x; ac2.y += wz * fa.y; ac2.z += wz * fb.x; ac2.w += wz * fb.y;
        ac3.x += ww * fa.x; ac3.y += ww * fa.y; ac3.z += ww * fb.x; ac3.w += ww * fb.y;
        ws0 += wx; ws1 += wy; ws2 += wz; ws3 += ww;
    }
    bool has = end > start;
    float i0 = has ? (1.f / ws0) : 0.f;
    float i1 = has ? (1.f / ws1) : 0.f;
    float i2 = has ? (1.f / ws2) : 0.f;
    float i3 = has ? (1.f / ws3) : 0.f;
    __half* O = g_aggx + (size_t)n * F1 + lane * 4;
    {
        __half2 h0 = __floats2half2_rn(ac0.x * i0, ac0.y * i0);
        __half2 h1 = __floats2half2_rn(ac0.z * i0, ac0.w * i0);
        *(uint2*)(O + 0 * 128) = make_uint2(*(uint32_t*)&h0, *(uint32_t*)&h1);
    }
    {
        __half2 h0 = __floats2half2_rn(ac1.x * i1, ac1.y * i1);
        __half2 h1 = __floats2half2_rn(ac1.z * i1, ac1.w * i1);
        *(uint2*)(O + 1 * 128) = make_uint2(*(uint32_t*)&h0, *(uint32_t*)&h1);
    }
    {
        __half2 h0 = __floats2half2_rn(ac2.x * i2, ac2.y * i2);
        __half2 h1 = __floats2half2_rn(ac2.z * i2, ac2.w * i2);
        *(uint2*)(O + 2 * 128) = make_uint2(*(uint32_t*)&h0, *(uint32_t*)&h1);
    }
    {
        __half2 h0 = __floats2half2_rn(ac3.x * i3, ac3.y * i3);
        __half2 h1 = __floats2half2_rn(ac3.z * i3, ac3.w * i3);
        *(uint2*)(O + 3 * 128) = make_uint2(*(uint32_t*)&h0, *(uint32_t*)&h1);
    }
}

// ---------------- HMMA fp16 GEMM, cp.async double-buffered, strided operands ----------
// BM=128, BN=64, BK=32; 8 warps (4m x 2n), 32x32 per warp.
// OUTMODE 2: plain fp16 store + fused el2/er2 score atomics (layer-2 GEMM)
// OUTMODE 3: ELU applied, fp16 store, no scores (layer-1 aggx@W1)
template<int K, int OUTMODE>
__device__ __forceinline__ void gemm_body(const __half* __restrict__ A, int lda,
                                          const __half* __restrict__ B, int ldb,
                                          __half* __restrict__ Ch, int ldc, int M,
                                          const float* __restrict__ al,
                                          const float* __restrict__ ar,
                                          int rowBase, int colBase) {
    __shared__ __half As[2][128][40];  // +8 pad
    __shared__ __half Bs[2][32][72];   // +8 pad
    int tid = threadIdx.x;
    int lane = tid & 31, wid = tid >> 5;
    int wm = wid >> 1, wn = wid & 1;

    float acc[2][4][4];
    #pragma unroll
    for (int a = 0; a < 2; a++)
        #pragma unroll
        for (int b = 0; b < 4; b++)
            #pragma unroll
            for (int c = 0; c < 4; c++) acc[a][b][c] = 0.f;

    uint32_t as_base = (uint32_t)__cvta_generic_to_shared(&As[0][0][0]);
    uint32_t bs_base = (uint32_t)__cvta_generic_to_shared(&Bs[0][0][0]);

    auto load_tiles = [&](int kt, int b) {
        #pragma unroll
        for (int hh = 0; hh < 2; hh++) {
            int r = (tid >> 2) + hh * 64;
            int grow = rowBase + r;
            if (grow >= M) grow = M - 1;
            cp16(as_base + (uint32_t)(((b << 7) + r) * 40 + (tid & 3) * 8) * 2,
                 A + (size_t)grow * lda + kt + (tid & 3) * 8);
        }
        int r = tid >> 3, c = (tid & 7) * 8;
        cp16(bs_base + (uint32_t)(((b << 5) + r) * 72 + c) * 2,
             B + (size_t)(kt + r) * ldb + colBase + c);
    };

    int g = lane >> 3;
    int arow_l = (lane & 7) + ((g & 1) ? 8 : 0);
    int acol_l = (g & 2) ? 8 : 0;
    int brow_l = ((g & 1) ? 8 : 0) + (lane & 7);
    int bcol_l = (g & 2) ? 8 : 0;

    const int NIT = K / 32;
    load_tiles(0, 0);
    cp_commit();
    int buf = 0;
    for (int it = 0; it < NIT; it++) {
        if (it + 1 < NIT) {
            load_tiles((it + 1) * 32, buf ^ 1);
            cp_commit();
            cp_wait1();
        } else {
            cp_wait0();
        }
        __syncthreads();
        #pragma unroll
        for (int kk = 0; kk < 2; kk++) {
            uint32_t af[2][4], bf[4][2];
            #pragma unroll
            for (int mi = 0; mi < 2; mi++) {
                int arow = wm * 32 + mi * 16 + arow_l;
                int acol = kk * 16 + acol_l;
                ldsm_x4(af[mi], as_base + (uint32_t)(((buf << 7) + arow) * 40 + acol) * 2);
            }
            #pragma unroll
            for (int n2 = 0; n2 < 2; n2++) {
                int kr = kk * 16 + brow_l;
                int nc = wn * 32 + n2 * 16 + bcol_l;
                uint32_t r4[4];
                ldsm_x4_t(r4, bs_base + (uint32_t)(((buf << 5) + kr) * 72 + nc) * 2);
                bf[n2 * 2][0] = r4[0]; bf[n2 * 2][1] = r4[1];
                bf[n2 * 2 + 1][0] = r4[2]; bf[n2 * 2 + 1][1] = r4[3];
            }
            #pragma unroll
            for (int mi = 0; mi < 2; mi++)
                #pragma unroll
                for (int nf = 0; nf < 4; nf++)
                    mma16816(acc[mi][nf], af[mi], bf[nf]);
        }
        __syncthreads();
        buf ^= 1;
    }

    int lr = lane >> 2, lc = (lane & 3) * 2;

    if constexpr (OUTMODE == 3) {
        // ELU + store
        #pragma unroll
        for (int mi = 0; mi < 2; mi++) {
            #pragma unroll
            for (int nf = 0; nf < 4; nf++) {
                int r0 = rowBase + wm * 32 + mi * 16 + lr;
                int cc = colBase + wn * 32 + nf * 8 + lc;
                float v0 = acc[mi][nf][0], v1 = acc[mi][nf][1];
                float v2 = acc[mi][nf][2], v3 = acc[mi][nf][3];
                v0 = v0 > 0.f ? v0 : expm1f(v0);
                v1 = v1 > 0.f ? v1 : expm1f(v1);
                v2 = v2 > 0.f ? v2 : expm1f(v2);
                v3 = v3 > 0.f ? v3 : expm1f(v3);
                if (r0 < M)
                    *(__half2*)(Ch + (size_t)r0 * ldc + cc) = __floats2half2_rn(v0, v1);
                if (r0 + 8 < M)
                    *(__half2*)(Ch + (size_t)(r0 + 8) * ldc + cc) = __floats2half2_rn(v2, v3);
            }
        }
    } else {
        // store + fused el2/er2 score epilogue
        float sel[4] = {0.f, 0.f, 0.f, 0.f};
        float ser[4] = {0.f, 0.f, 0.f, 0.f};
        #pragma unroll
        for (int mi = 0; mi < 2; mi++) {
            #pragma unroll
            for (int nf = 0; nf < 4; nf++) {
                int r0 = rowBase + wm * 32 + mi * 16 + lr;
                int cc = colBase + wn * 32 + nf * 8 + lc;
                float a0 = __ldg(&al[cc]),  a1 = __ldg(&al[cc + 1]);
                float r0a = __ldg(&ar[cc]), r1a = __ldg(&ar[cc + 1]);
                if (r0 < M)
                    *(__half2*)(Ch + (size_t)r0 * ldc + cc) =
                        __floats2half2_rn(acc[mi][nf][0], acc[mi][nf][1]);
                if (r0 + 8 < M)
                    *(__half2*)(Ch + (size_t)(r0 + 8) * ldc + cc) =
                        __floats2half2_rn(acc[mi][nf][2], acc[mi][nf][3]);
                sel[mi * 2]     += acc[mi][nf][0] * a0  + acc[mi][nf][1] * a1;
                sel[mi * 2 + 1] += acc[mi][nf][2] * a0  + acc[mi][nf][3] * a1;
                ser[mi * 2]     += acc[mi][nf][0] * r0a + acc[mi][nf][1] * r1a;
                ser[mi * 2 + 1] += acc[mi][nf][2] * r0a + acc[mi][nf][3] * r1a;
            }
        }
        #pragma unroll
        for (int q = 0; q < 4; q++) {
            sel[q] += __shfl_xor_sync(0xffffffffu, sel[q], 1);
            sel[q] += __shfl_xor_sync(0xffffffffu, sel[q], 2);
            ser[q] += __shfl_xor_sync(0xffffffffu, ser[q], 1);
            ser[q] += __shfl_xor_sync(0xffffffffu, ser[q], 2);
        }
        if ((lane & 3) == 0) {
            #pragma unroll
            for (int q = 0; q < 4; q++) {
                int r = rowBase + wm * 32 + (q >> 1) * 16 + (q & 1) * 8 + lr;
                if (r < M) {
                    atomicAdd(&g_el2[r], sel[q]);
                    atomicAdd(&g_er2[r], ser[q]);
                }
            }
        }
    }
}

// ---------------- launch 7: h1 = ELU(aggx_h @ W1_h), 4 batched GEMMs ----------------
__global__ __launch_bounds__(256) void k_gemmelu() {
    int h = blockIdx.z;
    gemm_body<128, 3>(g_aggx + h * 128, F1, g_w1h + h * 128, F1,
                      g_h1h + h * 128, F1, NN, nullptr, nullptr,
                      blockIdx.y * 128, blockIdx.x * 64);
}

// ---------------- launch 8: feat2 = h1 @ W2, fused el2/er2 scores ----------------
__global__ __launch_bounds__(256) void k_gemm2h(const float* __restrict__ al,
                                                const float* __restrict__ ar) {
    gemm_body<512, 2>(g_h1h, F1, g_w2h, F2, g_feat2h, F2, NN, al, ar,
                      blockIdx.y * 128, 0);
}

// ---------------- launch 9: layer2 aggregation (fp16 gather) -> d_out ----------------
__global__ __launch_bounds__(256) void k_agg2(float* __restrict__ out) {
    int n = blockIdx.x * 8 + (threadIdx.x >> 5);
    int lane = threadIdx.x & 31;
    if (n >= NN) return;
    int start = g_rowptr[n], end = g_rowptr[n + 1];
    float er_n = g_er2[n];
    float ax = 0.f, ay = 0.f, ws = 0.f;
    int k = start;
    for (; k + 7 < end; k += 8) {
        int sl = 0; float wv = 0.f;
        if (lane < 8) {
            sl = __ldg(&g_ssrc[k + lane]);
            wv = __expf(lrelu(__ldg(&g_el2[sl]) + er_n));
        }
        int s0 = __shfl_sync(0xffffffffu, sl, 0);
        int s1 = __shfl_sync(0xffffffffu, sl, 1);
        int s2 = __shfl_sync(0xffffffffu, sl, 2);
        int s3 = __shfl_sync(0xffffffffu, sl, 3);
        int s4 = __shfl_sync(0xffffffffu, sl, 4);
        int s5 = __shfl_sync(0xffffffffu, sl, 5);
        int s6 = __shfl_sync(0xffffffffu, sl, 6);
        int s7 = __shfl_sync(0xffffffffu, sl, 7);
        float w0 = __shfl_sync(0xffffffffu, wv, 0);
        float w1 = __shfl_sync(0xffffffffu, wv, 1);
        float w2 = __shfl_sync(0xffffffffu, wv, 2);
        float w3 = __shfl_sync(0xffffffffu, wv, 3);
        float w4 = __shfl_sync(0xffffffffu, wv, 4);
        float w5 = __shfl_sync(0xffffffffu, wv, 5);
        float w6 = __shfl_sync(0xffffffffu, wv, 6);
        float w7 = __shfl_sync(0xffffffffu, wv, 7);
        uint32_t r0 = __ldg((const uint32_t*)(g_feat2h + (size_t)s0 * F2) + lane);
        uint32_t r1 = __ldg((const uint32_t*)(g_feat2h + (size_t)s1 * F2) + lane);
        uint32_t r2 = __ldg((const uint32_t*)(g_feat2h + (size_t)s2 * F2) + lane);
        uint32_t r3 = __ldg((const uint32_t*)(g_feat2h + (size_t)s3 * F2) + lane);
        uint32_t r4 = __ldg((const uint32_t*)(g_feat2h + (size_t)s4 * F2) + lane);
        uint32_t r5 = __ldg((const uint32_t*)(g_feat2h + (size_t)s5 * F2) + lane);
        uint32_t r6 = __ldg((const uint32_t*)(g_feat2h + (size_t)s6 * F2) + lane);
        uint32_t r7 = __ldg((const uint32_t*)(g_feat2h + (size_t)s7 * F2) + lane);
        float2 f;
        f = __half22float2(*(__half2*)&r0); ax += w0 * f.x; ay += w0 * f.y;
        f = __half22float2(*(__half2*)&r1); ax += w1 * f.x; ay += w1 * f.y;
        f = __half22float2(*(__half2*)&r2); ax += w2 * f.x; ay += w2 * f.y;
        f = __half22float2(*(__half2*)&r3); ax += w3 * f.x; ay += w3 * f.y;
        f = __half22float2(*(__half2*)&r4); ax += w4 * f.x; ay += w4 * f.y;
        f = __half22float2(*(__half2*)&r5); ax += w5 * f.x; ay += w5 * f.y;
        f = __half22float2(*(__half2*)&r6); ax += w6 * f.x; ay += w6 * f.y;
        f = __half22float2(*(__half2*)&r7); ax += w7 * f.x; ay += w7 * f.y;
        ws += w0 + w1 + w2 + w3 + w4 + w5 + w6 + w7;
    }
    if (k + 3 < end) {
        int sl = 0; float wv = 0.f;
        if (lane < 4) {
            sl = __ldg(&g_ssrc[k + lane]);
            wv = __expf(lrelu(__ldg(&g_el2[sl]) + er_n));
        }
        int s0 = __shfl_sync(0xffffffffu, sl, 0);
        int s1 = __shfl_sync(0xffffffffu, sl, 1);
        int s2 = __shfl_sync(0xffffffffu, sl, 2);
        int s3 = __shfl_sync(0xffffffffu, sl, 3);
        float w0 = __shfl_sync(0xffffffffu, wv, 0);
        float w1 = __shfl_sync(0xffffffffu, wv, 1);
        float w2 = __shfl_sync(0xffffffffu, wv, 2);
        float w3 = __shfl_sync(0xffffffffu, wv, 3);
        uint32_t r0 = __ldg((const uint32_t*)(g_feat2h + (size_t)s0 * F2) + lane);
        uint32_t r1 = __ldg((const uint32_t*)(g_feat2h + (size_t)s1 * F2) + lane);
        uint32_t r2 = __ldg((const uint32_t*)(g_feat2h + (size_t)s2 * F2) + lane);
        uint32_t r3 = __ldg((const uint32_t*)(g_feat2h + (size_t)s3 * F2) + lane);
        float2 f;
        f = __half22float2(*(__half2*)&r0); ax += w0 * f.x; ay += w0 * f.y;
        f = __half22float2(*(__half2*)&r1); ax += w1 * f.x; ay += w1 * f.y;
        f = __half22float2(*(__half2*)&r2); ax += w2 * f.x; ay += w2 * f.y;
        f = __half22float2(*(__half2*)&r3); ax += w3 * f.x; ay += w3 * f.y;
        ws += w0 + w1 + w2 + w3;
        k += 4;
    }
    for (; k < end; k++) {
        int sl = 0; float wv = 0.f;
        if (lane == 0) {
            sl = __ldg(&g_ssrc[k]);
            wv = __expf(lrelu(__ldg(&g_el2[sl]) + er_n));
        }
        int s0 = __shfl_sync(0xffffffffu, sl, 0);
        float w0 = __shfl_sync(0xffffffffu, wv, 0);
        uint32_t r0 = __ldg((const uint32_t*)(g_feat2h + (size_t)s0 * F2) + lane);
        float2 f0 = __half22float2(*(__half2*)&r0);
        ax += w0 * f0.x; ay += w0 * f0.y;
        ws += w0;
    }
    float sv = (end > start) ? (1.f / ws) : 0.f;
    *(float2*)(out + (size_t)n * F2 + lane * 2) = make_float2(ax * sv, ay * sv);
}

// ---------------- launch ----------------
extern "C" void kernel_launch(void* const* d_in, const int* in_sizes, int n_in,
                              void* d_out, int out_size) {
    const float* x   = (const float*)d_in[0];
    const float* W1  = (const float*)d_in[1];
    const float* al1 = (const float*)d_in[2];
    const float* ar1 = (const float*)d_in[3];
    const float* W2  = (const float*)d_in[4];
    const float* al2 = (const float*)d_in[5];
    const float* ar2 = (const float*)d_in[6];
    const void*  src = d_in[7];
    const void*  dst = d_in[8];
    float* out = (float*)d_out;

    const int WB = (NN + 7) / 8;                // 12500
    const int MTILES = (NN + 127) / 128;        // 782

    // 1: detect + zero deg / el2 / er2
    k_setup0<<<1 + (NN + 255) / 256, 256>>>((const long long*)src);
    // 2: conv || cast || v-vector precompute
    k_setup1<<<EBLK * 2 + 8, 256>>>((const float4*)x, (const float4*)W1, (const float4*)W2,
                                    src, dst, al1, ar1);
    // 3: rowptr scan
    k_scan<<<1, 1024>>>();
    // 4 (profiled): CSR scatter
    k_scatter<<<EBLK, 256>>>();
    // 5: layer1 scores from v-vectors
    k_score1<<<WB, 256>>>();
    // 6: aggregate x (256B/edge, all heads share one gather)
    k_aggx<<<WB, 256>>>();
    // 7: h1 = ELU(aggx @ W1) — 4 batched 128-wide GEMMs
    k_gemmelu<<<dim3(2, MTILES, 4), 256>>>();
    // 8: feat2 = h1 @ W2 + fused scores
    k_gemm2h<<<dim3(1, MTILES), 256>>>(al2, ar2);
    // 9: layer2 aggregation -> out
    k_agg2<<<WB, 256>>>(out);
}

// round 13
// speedup vs baseline: 1.1794x; 1.0479x over previous
#include <cuda_runtime.h>
#include <cuda_fp16.h>
#include <math.h>
#include <stdint.h>

// Problem constants (fixed by the reference)
#define NN 100000
#define NE 3200000
#define H1 4
#define D1 128
#define F1 512     // H1*D1
#define F2 64
#define NEG_SLOPE 0.2f

// ---------------- scratch (static __device__ arrays; allocation is forbidden) ----------------
__device__ __align__(16) __half g_xh[(size_t)NN * D1];      // x in fp16 (25.6 MB, L2-resident gather table)
__device__ __align__(16) __half g_w1h[D1 * F1];             // W1 fp16
__device__ __align__(16) __half g_w2h[F1 * F2];             // W2 fp16
__device__ __align__(16) __half g_aggx[(size_t)NN * F1];    // (Σ w·x)/S per (node,head): [N][H*128] fp16
__device__ __align__(16) __half g_h1h[(size_t)NN * F1];     // ELU(aggx@W1) fp16, node-major [N][512]
__device__ __align__(16) __half g_feat2h[(size_t)NN * F2];  // layer2 linear out fp16 (12.8 MB)
__device__ __align__(16) float g_vl[F1], g_vr[F1];          // W1_h @ al_h / ar_h, [h*128+i]
__device__ __align__(16) float4 g_els[NN];                  // el1 per node, 4 heads
__device__ __align__(16) float4 g_ers[NN];                  // er1 per node, 4 heads
__device__ __align__(16) float4 g_w4[NE];                   // layer1 edge weights, CSR order (51.2 MB)
__device__ float g_el2[NN], g_er2[NN];
__device__ int g_src32[NE], g_dst32[NE];   // int32 index mirrors
__device__ int g_ssrc[NE];                 // src id per CSR slot
__device__ int g_sdst[NE];                 // dst id per CSR slot
__device__ int g_deg[NN];
__device__ int g_rowptr[NN + 1];
__device__ int g_cursor[NN];
__device__ int g_mode;                     // 0 = int64 indices, 1 = int32 indices

// ---------------- helpers ----------------
__device__ __forceinline__ float lrelu(float x) { return x >= 0.f ? x : NEG_SLOPE * x; }

__device__ __forceinline__ void ldsm_x4(uint32_t r[4], uint32_t addr) {
    asm volatile("ldmatrix.sync.aligned.m8n8.x4.shared.b16 {%0,%1,%2,%3}, [%4];"
                 : "=r"(r[0]), "=r"(r[1]), "=r"(r[2]), "=r"(r[3]) : "r"(addr));
}
__device__ __forceinline__ void ldsm_x4_t(uint32_t r[4], uint32_t addr) {
    asm volatile("ldmatrix.sync.aligned.m8n8.x4.trans.shared.b16 {%0,%1,%2,%3}, [%4];"
                 : "=r"(r[0]), "=r"(r[1]), "=r"(r[2]), "=r"(r[3]) : "r"(addr));
}
__device__ __forceinline__ void mma16816(float c[4], const uint32_t a[4], const uint32_t b[2]) {
    asm volatile("mma.sync.aligned.m16n8k16.row.col.f32.f16.f16.f32 "
                 "{%0,%1,%2,%3}, {%4,%5,%6,%7}, {%8,%9}, {%0,%1,%2,%3};"
                 : "+f"(c[0]), "+f"(c[1]), "+f"(c[2]), "+f"(c[3])
                 : "r"(a[0]), "r"(a[1]), "r"(a[2]), "r"(a[3]), "r"(b[0]), "r"(b[1]));
}
__device__ __forceinline__ void cp16(uint32_t smem, const void* g) {
    asm volatile("cp.async.cg.shared.global [%0], [%1], 16;" :: "r"(smem), "l"(g));
}
__device__ __forceinline__ void cp_commit() { asm volatile("cp.async.commit_group;"); }
__device__ __forceinline__ void cp_wait1() { asm volatile("cp.async.wait_group 1;"); }
__device__ __forceinline__ void cp_wait0() { asm volatile("cp.async.wait_group 0;"); }

// ---------------- launch 1: detect index width + zero deg / layer2 score accumulators ------
__global__ void k_setup0(const long long* __restrict__ src) {
    if (blockIdx.x == 0) {
        if (threadIdx.x == 0) {
            int m = 0;
            for (int i = 0; i < 256; i++) {
                long long v = src[i];
                if (v < 0 || v >= NN) { m = 1; break; }
            }
            g_mode = m;
        }
        return;
    }
    int i = (blockIdx.x - 1) * blockDim.x + threadIdx.x;
    if (i < NN) { g_deg[i] = 0; g_el2[i] = 0.f; g_er2[i] = 0.f; }
}

// ---------------- launch 2: conv || cast || score-vector precompute ----------------
__device__ __forceinline__ uint2 f4toh(float4 v) {
    __half2 a = __floats2half2_rn(v.x, v.y);
    __half2 b = __floats2half2_rn(v.z, v.w);
    uint2 r;
    r.x = *(uint32_t*)&a;
    r.y = *(uint32_t*)&b;
    return r;
}
#define EBLK 12500
__global__ void k_setup1(const float4* __restrict__ x, const float4* __restrict__ w1,
                         const float4* __restrict__ w2,
                         const void* __restrict__ srcp, const void* __restrict__ dstp,
                         const float* __restrict__ al1, const float* __restrict__ ar1) {
    if (blockIdx.x < EBLK) {
        // conv: widen indices + degree histogram
        int i = blockIdx.x * blockDim.x + threadIdx.x;
        if (i >= NE) return;
        int s, d;
        if (g_mode) {
            s = ((const int*)srcp)[i];
            d = ((const int*)dstp)[i];
        } else {
            s = (int)((const long long*)srcp)[i];
            d = (int)((const long long*)dstp)[i];
        }
        g_src32[i] = s;
        g_dst32[i] = d;
        atomicAdd(&g_deg[d], 1);
    } else if (blockIdx.x < 2 * EBLK) {
        // cast x, W1, W2 to fp16
        int i = (blockIdx.x - EBLK) * blockDim.x + threadIdx.x;
        if (i < NN * D1 / 4) ((uint2*)g_xh)[i]  = f4toh(x[i]);
        if (i < D1 * F1 / 4) ((uint2*)g_w1h)[i] = f4toh(w1[i]);
        if (i < F1 * F2 / 4) ((uint2*)g_w2h)[i] = f4toh(w2[i]);
    } else {
        // v-vectors: block b in [0,8): h = b&3, r-side = b>>2
        int b = blockIdx.x - 2 * EBLK;      // 0..7
        int h = b & 3;
        const float* W1f = (const float*)w1;
        const float* a = (b >> 2) ? ar1 : al1;
        float* v = (b >> 2) ? g_vr : g_vl;
        int i = threadIdx.x;                // 0..255, need 0..127
        if (i < 128) {
            float sum = 0.f;
            #pragma unroll 4
            for (int d = 0; d < 128; d++)
                sum += W1f[i * F1 + h * 128 + d] * a[h * 128 + d];
            v[h * 128 + i] = sum;
        }
    }
}

// ---------------- launch 3: parallel exclusive scan of degrees ----------------
__global__ __launch_bounds__(1024) void k_scan() {
    const int PER = (NN + 1023) / 1024;  // 98
    int tid = threadIdx.x, lane = tid & 31, wid = tid >> 5;
    int base = tid * PER;
    int sum = 0;
    for (int j = 0; j < PER; j++) {
        int i = base + j;
        if (i < NN) sum += g_deg[i];
    }
    int incl = sum;
    #pragma unroll
    for (int o = 1; o < 32; o <<= 1) {
        int t = __shfl_up_sync(0xffffffffu, incl, o);
        if (lane >= o) incl += t;
    }
    __shared__ int wsum[32];
    if (lane == 31) wsum[wid] = incl;
    __syncthreads();
    if (wid == 0) {
        int v = wsum[lane];
        int z = v;
        #pragma unroll
        for (int o = 1; o < 32; o <<= 1) {
            int t = __shfl_up_sync(0xffffffffu, z, o);
            if (lane >= o) z += t;
        }
        wsum[lane] = z - v;
    }
    __syncthreads();
    int run = incl - sum + wsum[wid];
    for (int j = 0; j < PER; j++) {
        int i = base + j;
        if (i < NN) {
            g_rowptr[i] = run;
            g_cursor[i] = run;
            run += g_deg[i];
        }
    }
    if (tid == 1023) g_rowptr[NN] = run;
}

// ---------------- launch 4: CSR scatter (src + dst per slot) ----------------
__global__ void k_scatter() {
    int i = blockIdx.x * blockDim.x + threadIdx.x;
    if (i >= NE) return;
    int d = g_dst32[i];
    int pos = atomicAdd(&g_cursor[d], 1);
    g_ssrc[pos] = g_src32[i];
    g_sdst[pos] = d;
}

// ---------------- launch 5: layer1 scores via precomputed v-vectors ----------------
// el[n,h] = x[n]·vl[h];  er[n,h] = x[n]·vr[h].  Warp per node.
__global__ __launch_bounds__(256) void k_score1() {
    int w = (blockIdx.x * blockDim.x + threadIdx.x) >> 5;
    int lane = threadIdx.x & 31;
    if (w >= NN) return;
    uint2 xv = __ldg((const uint2*)(g_xh + (size_t)w * D1) + lane);
    __half2* p = (__half2*)&xv;
    float2 xa = __half22float2(p[0]);
    float2 xb = __half22float2(p[1]);
    float el[4], er[4];
    #pragma unroll
    for (int h = 0; h < 4; h++) {
        float4 vl = *(const float4*)&g_vl[h * 128 + lane * 4];
        float4 vr = *(const float4*)&g_vr[h * 128 + lane * 4];
        el[h] = xa.x * vl.x + xa.y * vl.y + xb.x * vl.z + xb.y * vl.w;
        er[h] = xa.x * vr.x + xa.y * vr.y + xb.x * vr.z + xb.y * vr.w;
    }
    #pragma unroll
    for (int o = 16; o > 0; o >>= 1) {
        #pragma unroll
        for (int h = 0; h < 4; h++) {
            el[h] += __shfl_xor_sync(0xffffffffu, el[h], o);
            er[h] += __shfl_xor_sync(0xffffffffu, er[h], o);
        }
    }
    if (lane == 0) {
        g_els[w] = make_float4(el[0], el[1], el[2], el[3]);
        g_ers[w] = make_float4(er[0], er[1], er[2], er[3]);
    }
}

// ---------------- launch 6: edge weights, CSR order, edge-parallel ----------------
// w4[i] = exp(lrelu(els[ssrc[i]] + ers[sdst[i]])).  Streaming; breaks the dep chain
// out of the aggregation gather loop.
__global__ void k_wgt() {
    int i = blockIdx.x * blockDim.x + threadIdx.x;
    if (i >= NE) return;
    int s = g_ssrc[i];
    int d = g_sdst[i];
    float4 e = __ldg(&g_els[s]);
    float4 r = __ldg(&g_ers[d]);
    float4 w;
    w.x = __expf(lrelu(e.x + r.x));
    w.y = __expf(lrelu(e.y + r.y));
    w.z = __expf(lrelu(e.z + r.z));
    w.w = __expf(lrelu(e.w + r.w));
    g_w4[i] = w;
}

// ---------------- launch 7: aggregate x with precomputed weights ----------------
// Warp per node; 8-edge batches; gathers issued back-to-back (MLP=8); weights are
// uniform broadcast L1 loads; NO shfl, NO exp in the loop.
__device__ __forceinline__ void accum_x(float4 w, uint2 r, float4 ac[4], float ws[4]) {
    __half2* p = (__half2*)&r;
    float2 fa = __half22float2(p[0]);
    float2 fb = __half22float2(p[1]);
    ac[0].x += w.x * fa.x; ac[0].y += w.x * fa.y; ac[0].z += w.x * fb.x; ac[0].w += w.x * fb.y;
    ac[1].x += w.y * fa.x; ac[1].y += w.y * fa.y; ac[1].z += w.y * fb.x; ac[1].w += w.y * fb.y;
    ac[2].x += w.z * fa.x; ac[2].y += w.z * fa.y; ac[2].z += w.z * fb.x; ac[2].w += w.z * fb.y;
    ac[3].x += w.w * fa.x; ac[3].y += w.w * fa.y; ac[3].z += w.w * fb.x; ac[3].w += w.w * fb.y;
    ws[0] += w.x; ws[1] += w.y; ws[2] += w.z; ws[3] += w.w;
}
__global__ __launch_bounds__(256) void k_aggx() {
    int n = blockIdx.x * 8 + (threadIdx.x >> 5);
    int lane = threadIdx.x & 31;
    if (n >= NN) return;
    int start = g_rowptr[n], end = g_rowptr[n + 1];
    float4 ac[4] = {{0,0,0,0},{0,0,0,0},{0,0,0,0},{0,0,0,0}};
    float ws[4] = {0,0,0,0};
    int k = start;
    for (; k + 7 < end; k += 8) {
        int s0 = __ldg(&g_ssrc[k + 0]);
        int s1 = __ldg(&g_ssrc[k + 1]);
        int s2 = __ldg(&g_ssrc[k + 2]);
        int s3 = __ldg(&g_ssrc[k + 3]);
        int s4 = __ldg(&g_ssrc[k + 4]);
        int s5 = __ldg(&g_ssrc[k + 5]);
        int s6 = __ldg(&g_ssrc[k + 6]);
        int s7 = __ldg(&g_ssrc[k + 7]);
        uint2 r0 = __ldg((const uint2*)(g_xh + (size_t)s0 * D1) + lane);
        uint2 r1 = __ldg((const uint2*)(g_xh + (size_t)s1 * D1) + lane);
        uint2 r2 = __ldg((const uint2*)(g_xh + (size_t)s2 * D1) + lane);
        uint2 r3 = __ldg((const uint2*)(g_xh + (size_t)s3 * D1) + lane);
        uint2 r4 = __ldg((const uint2*)(g_xh + (size_t)s4 * D1) + lane);
        uint2 r5 = __ldg((const uint2*)(g_xh + (size_t)s5 * D1) + lane);
        uint2 r6 = __ldg((const uint2*)(g_xh + (size_t)s6 * D1) + lane);
        uint2 r7 = __ldg((const uint2*)(g_xh + (size_t)s7 * D1) + lane);
        accum_x(__ldg(&g_w4[k + 0]), r0, ac, ws);
        accum_x(__ldg(&g_w4[k + 1]), r1, ac, ws);
        accum_x(__ldg(&g_w4[k + 2]), r2, ac, ws);
        accum_x(__ldg(&g_w4[k + 3]), r3, ac, ws);
        accum_x(__ldg(&g_w4[k + 4]), r4, ac, ws);
        accum_x(__ldg(&g_w4[k + 5]), r5, ac, ws);
        accum_x(__ldg(&g_w4[k + 6]), r6, ac, ws);
        accum_x(__ldg(&g_w4[k + 7]), r7, ac, ws);
    }
    if (k + 3 < end) {
        int s0 = __ldg(&g_ssrc[k + 0]);
        int s1 = __ldg(&g_ssrc[k + 1]);
        int s2 = __ldg(&g_ssrc[k + 2]);
        int s3 = __ldg(&g_ssrc[k + 3]);
        uint2 r0 = __ldg((const uint2*)(g_xh + (size_t)s0 * D1) + lane);
        uint2 r1 = __ldg((const uint2*)(g_xh + (size_t)s1 * D1) + lane);
        uint2 r2 = __ldg((const uint2*)(g_xh + (size_t)s2 * D1) + lane);
        uint2 r3 = __ldg((const uint2*)(g_xh + (size_t)s3 * D1) + lane);
        accum_x(__ldg(&g_w4[k + 0]), r0, ac, ws);
        accum_x(__ldg(&g_w4[k + 1]), r1, ac, ws);
        accum_x(__ldg(&g_w4[k + 2]), r2, ac, ws);
        accum_x(__ldg(&g_w4[k + 3]), r3, ac, ws);
        k += 4;
    }
    for (; k < end; k++) {
        int s0 = __ldg(&g_ssrc[k]);
        uint2 r0 = __ldg((const uint2*)(g_xh + (size_t)s0 * D1) + lane);
        accum_x(__ldg(&g_w4[k]), r0, ac, ws);
    }
    bool has = end > start;
    __half* O = g_aggx + (size_t)n * F1 + lane * 4;
    #pragma unroll
    for (int h = 0; h < 4; h++) {
        float iv = has ? (1.f / ws[h]) : 0.f;
        __half2 h0 = __floats2half2_rn(ac[h].x * iv, ac[h].y * iv);
        __half2 h1 = __floats2half2_rn(ac[h].z * iv, ac[h].w * iv);
        *(uint2*)(O + h * 128) = make_uint2(*(uint32_t*)&h0, *(uint32_t*)&h1);
    }
}

// ---------------- HMMA fp16 GEMM, cp.async double-buffered, strided operands ----------
// BM=128, BN=64, BK=32; 8 warps (4m x 2n), 32x32 per warp.
// OUTMODE 2: plain fp16 store + fused el2/er2 score atomics (layer-2 GEMM)
// OUTMODE 3: ELU applied, fp16 store, no scores (layer-1 aggx@W1)
template<int K, int OUTMODE>
__device__ __forceinline__ void gemm_body(const __half* __restrict__ A, int lda,
                                          const __half* __restrict__ B, int ldb,
                                          __half* __restrict__ Ch, int ldc, int M,
                                          const float* __restrict__ al,
                                          const float* __restrict__ ar,
                                          int rowBase, int colBase) {
    __shared__ __half As[2][128][40];  // +8 pad
    __shared__ __half Bs[2][32][72];   // +8 pad
    int tid = threadIdx.x;
    int lane = tid & 31, wid = tid >> 5;
    int wm = wid >> 1, wn = wid & 1;

    float acc[2][4][4];
    #pragma unroll
    for (int a = 0; a < 2; a++)
        #pragma unroll
        for (int b = 0; b < 4; b++)
            #pragma unroll
            for (int c = 0; c < 4; c++) acc[a][b][c] = 0.f;

    uint32_t as_base = (uint32_t)__cvta_generic_to_shared(&As[0][0][0]);
    uint32_t bs_base = (uint32_t)__cvta_generic_to_shared(&Bs[0][0][0]);

    auto load_tiles = [&](int kt, int b) {
        #pragma unroll
        for (int hh = 0; hh < 2; hh++) {
            int r = (tid >> 2) + hh * 64;
            int grow = rowBase + r;
            if (grow >= M) grow = M - 1;
            cp16(as_base + (uint32_t)(((b << 7) + r) * 40 + (tid & 3) * 8) * 2,
                 A + (size_t)grow * lda + kt + (tid & 3) * 8);
        }
        int r = tid >> 3, c = (tid & 7) * 8;
        cp16(bs_base + (uint32_t)(((b << 5) + r) * 72 + c) * 2,
             B + (size_t)(kt + r) * ldb + colBase + c);
    };

    int g = lane >> 3;
    int arow_l = (lane & 7) + ((g & 1) ? 8 : 0);
    int acol_l = (g & 2) ? 8 : 0;
    int brow_l = ((g & 1) ? 8 : 0) + (lane & 7);
    int bcol_l = (g & 2) ? 8 : 0;

    const int NIT = K / 32;
    load_tiles(0, 0);
    cp_commit();
    int buf = 0;
    for (int it = 0; it < NIT; it++) {
        if (it + 1 < NIT) {
            load_tiles((it + 1) * 32, buf ^ 1);
            cp_commit();
            cp_wait1();
        } else {
            cp_wait0();
        }
        __syncthreads();
        #pragma unroll
        for (int kk = 0; kk < 2; kk++) {
            uint32_t af[2][4], bf[4][2];
            #pragma unroll
            for (int mi = 0; mi < 2; mi++) {
                int arow = wm * 32 + mi * 16 + arow_l;
                int acol = kk * 16 + acol_l;
                ldsm_x4(af[mi], as_base + (uint32_t)(((buf << 7) + arow) * 40 + acol) * 2);
            }
            #pragma unroll
            for (int n2 = 0; n2 < 2; n2++) {
                int kr = kk * 16 + brow_l;
                int nc = wn * 32 + n2 * 16 + bcol_l;
                uint32_t r4[4];
                ldsm_x4_t(r4, bs_base + (uint32_t)(((buf << 5) + kr) * 72 + nc) * 2);
                bf[n2 * 2][0] = r4[0]; bf[n2 * 2][1] = r4[1];
                bf[n2 * 2 + 1][0] = r4[2]; bf[n2 * 2 + 1][1] = r4[3];
            }
            #pragma unroll
            for (int mi = 0; mi < 2; mi++)
                #pragma unroll
                for (int nf = 0; nf < 4; nf++)
                    mma16816(acc[mi][nf], af[mi], bf[nf]);
        }
        __syncthreads();
        buf ^= 1;
    }

    int lr = lane >> 2, lc = (lane & 3) * 2;

    if constexpr (OUTMODE == 3) {
        // ELU + store
        #pragma unroll
        for (int mi = 0; mi < 2; mi++) {
            #pragma unroll
            for (int nf = 0; nf < 4; nf++) {
                int r0 = rowBase + wm * 32 + mi * 16 + lr;
                int cc = colBase + wn * 32 + nf * 8 + lc;
                float v0 = acc[mi][nf][0], v1 = acc[mi][nf][1];
                float v2 = acc[mi][nf][2], v3 = acc[mi][nf][3];
                v0 = v0 > 0.f ? v0 : expm1f(v0);
                v1 = v1 > 0.f ? v1 : expm1f(v1);
                v2 = v2 > 0.f ? v2 : expm1f(v2);
                v3 = v3 > 0.f ? v3 : expm1f(v3);
                if (r0 < M)
                    *(__half2*)(Ch + (size_t)r0 * ldc + cc) = __floats2half2_rn(v0, v1);
                if (r0 + 8 < M)
                    *(__half2*)(Ch + (size_t)(r0 + 8) * ldc + cc) = __floats2half2_rn(v2, v3);
            }
        }
    } else {
        // store + fused el2/er2 score epilogue
        float sel[4] = {0.f, 0.f, 0.f, 0.f};
        float ser[4] = {0.f, 0.f, 0.f, 0.f};
        #pragma unroll
        for (int mi = 0; mi < 2; mi++) {
            #pragma unroll
            for (int nf = 0; nf < 4; nf++) {
                int r0 = rowBase + wm * 32 + mi * 16 + lr;
                int cc = colBase + wn * 32 + nf * 8 + lc;
                float a0 = __ldg(&al[cc]),  a1 = __ldg(&al[cc + 1]);
                float r0a = __ldg(&ar[cc]), r1a = __ldg(&ar[cc + 1]);
                if (r0 < M)
                    *(__half2*)(Ch + (size_t)r0 * ldc + cc) =
                        __floats2half2_rn(acc[mi][nf][0], acc[mi][nf][1]);
                if (r0 + 8 < M)
                    *(__half2*)(Ch + (size_t)(r0 + 8) * ldc + cc) =
                        __floats2half2_rn(acc[mi][nf][2], acc[mi][nf][3]);
                sel[mi * 2]     += acc[mi][nf][0] * a0  + acc[mi][nf][1] * a1;
                sel[mi * 2 + 1] += acc[mi][nf][2] * a0  + acc[mi][nf][3] * a1;
                ser[mi * 2]     += acc[mi][nf][0] * r0a + acc[mi][nf][1] * r1a;
                ser[mi * 2 + 1] += acc[mi][nf][2] * r0a + acc[mi][nf][3] * r1a;
            }
        }
        #pragma unroll
        for (int q = 0; q < 4; q++) {
            sel[q] += __shfl_xor_sync(0xffffffffu, sel[q], 1);
            sel[q] += __shfl_xor_sync(0xffffffffu, sel[q], 2);
            ser[q] += __shfl_xor_sync(0xffffffffu, ser[q], 1);
            ser[q] += __shfl_xor_sync(0xffffffffu, ser[q], 2);
        }
        if ((lane & 3) == 0) {
            #pragma unroll
            for (int q = 0; q < 4; q++) {
                int r = rowBase + wm * 32 + (q >> 1) * 16 + (q & 1) * 8 + lr;
                if (r < M) {
                    atomicAdd(&g_el2[r], sel[q]);
                    atomicAdd(&g_er2[r], ser[q]);
                }
            }
        }
    }
}

// ---------------- launch 8: h1 = ELU(aggx_h @ W1_h), 4 batched GEMMs ----------------
__global__ __launch_bounds__(256) void k_gemmelu() {
    int h = blockIdx.z;
    gemm_body<128, 3>(g_aggx + h * 128, F1, g_w1h + h * 128, F1,
                      g_h1h + h * 128, F1, NN, nullptr, nullptr,
                      blockIdx.y * 128, blockIdx.x * 64);
}

// ---------------- launch 9: feat2 = h1 @ W2, fused el2/er2 scores ----------------
__global__ __launch_bounds__(256) void k_gemm2h(const float* __restrict__ al,
                                                const float* __restrict__ ar) {
    gemm_body<512, 2>(g_h1h, F1, g_w2h, F2, g_feat2h, F2, NN, al, ar,
                      blockIdx.y * 128, 0);
}

// ---------------- launch 10: layer2 aggregation (fp16 gather) -> d_out ----------------
__global__ __launch_bounds__(256) void k_agg2(float* __restrict__ out) {
    int n = blockIdx.x * 8 + (threadIdx.x >> 5);
    int lane = threadIdx.x & 31;
    if (n >= NN) return;
    int start = g_rowptr[n], end = g_rowptr[n + 1];
    float er_n = g_er2[n];
    float ax = 0.f, ay = 0.f, ws = 0.f;
    int k = start;
    for (; k + 7 < end; k += 8) {
        int sl = 0; float wv = 0.f;
        if (lane < 8) {
            sl = __ldg(&g_ssrc[k + lane]);
            wv = __expf(lrelu(__ldg(&g_el2[sl]) + er_n));
        }
        int s0 = __shfl_sync(0xffffffffu, sl, 0);
        int s1 = __shfl_sync(0xffffffffu, sl, 1);
        int s2 = __shfl_sync(0xffffffffu, sl, 2);
        int s3 = __shfl_sync(0xffffffffu, sl, 3);
        int s4 = __shfl_sync(0xffffffffu, sl, 4);
        int s5 = __shfl_sync(0xffffffffu, sl, 5);
        int s6 = __shfl_sync(0xffffffffu, sl, 6);
        int s7 = __shfl_sync(0xffffffffu, sl, 7);
        float w0 = __shfl_sync(0xffffffffu, wv, 0);
        float w1 = __shfl_sync(0xffffffffu, wv, 1);
        float w2 = __shfl_sync(0xffffffffu, wv, 2);
        float w3 = __shfl_sync(0xffffffffu, wv, 3);
        float w4 = __shfl_sync(0xffffffffu, wv, 4);
        float w5 = __shfl_sync(0xffffffffu, wv, 5);
        float w6 = __shfl_sync(0xffffffffu, wv, 6);
        float w7 = __shfl_sync(0xffffffffu, wv, 7);
        uint32_t r0 = __ldg((const uint32_t*)(g_feat2h + (size_t)s0 * F2) + lane);
        uint32_t r1 = __ldg((const uint32_t*)(g_feat2h + (size_t)s1 * F2) + lane);
        uint32_t r2 = __ldg((const uint32_t*)(g_feat2h + (size_t)s2 * F2) + lane);
        uint32_t r3 = __ldg((const uint32_t*)(g_feat2h + (size_t)s3 * F2) + lane);
        uint32_t r4 = __ldg((const uint32_t*)(g_feat2h + (size_t)s4 * F2) + lane);
        uint32_t r5 = __ldg((const uint32_t*)(g_feat2h + (size_t)s5 * F2) + lane);
        uint32_t r6 = __ldg((const uint32_t*)(g_feat2h + (size_t)s6 * F2) + lane);
        uint32_t r7 = __ldg((const uint32_t*)(g_feat2h + (size_t)s7 * F2) + lane);
        float2 f;
        f = __half22float2(*(__half2*)&r0); ax += w0 * f.x; ay += w0 * f.y;
        f = __half22float2(*(__half2*)&r1); ax += w1 * f.x; ay += w1 * f.y;
        f = __half22float2(*(__half2*)&r2); ax += w2 * f.x; ay += w2 * f.y;
        f = __half22float2(*(__half2*)&r3); ax += w3 * f.x; ay += w3 * f.y;
        f = __half22float2(*(__half2*)&r4); ax += w4 * f.x; ay += w4 * f.y;
        f = __half22float2(*(__half2*)&r5); ax += w5 * f.x; ay += w5 * f.y;
        f = __half22float2(*(__half2*)&r6); ax += w6 * f.x; ay += w6 * f.y;
        f = __half22float2(*(__half2*)&r7); ax += w7 * f.x; ay += w7 * f.y;
        ws += w0 + w1 + w2 + w3 + w4 + w5 + w6 + w7;
    }
    if (k + 3 < end) {
        int sl = 0; float wv = 0.f;
        if (lane < 4) {
            sl = __ldg(&g_ssrc[k + lane]);
            wv = __expf(lrelu(__ldg(&g_el2[sl]) + er_n));
        }
        int s0 = __shfl_sync(0xffffffffu, sl, 0);
        int s1 = __shfl_sync(0xffffffffu, sl, 1);
        int s2 = __shfl_sync(0xffffffffu, sl, 2);
        int s3 = __shfl_sync(0xffffffffu, sl, 3);
        float w0 = __shfl_sync(0xffffffffu, wv, 0);
        float w1 = __shfl_sync(0xffffffffu, wv, 1);
        float w2 = __shfl_sync(0xffffffffu, wv, 2);
        float w3 = __shfl_sync(0xffffffffu, wv, 3);
        uint32_t r0 = __ldg((const uint32_t*)(g_feat2h + (size_t)s0 * F2) + lane);
        uint32_t r1 = __ldg((const uint32_t*)(g_feat2h + (size_t)s1 * F2) + lane);
        uint32_t r2 = __ldg((const uint32_t*)(g_feat2h + (size_t)s2 * F2) + lane);
        uint32_t r3 = __ldg((const uint32_t*)(g_feat2h + (size_t)s3 * F2) + lane);
        float2 f;
        f = __half22float2(*(__half2*)&r0); ax += w0 * f.x; ay += w0 * f.y;
        f = __half22float2(*(__half2*)&r1); ax += w1 * f.x; ay += w1 * f.y;
        f = __half22float2(*(__half2*)&r2); ax += w2 * f.x; ay += w2 * f.y;
        f = __half22float2(*(__half2*)&r3); ax += w3 * f.x; ay += w3 * f.y;
        ws += w0 + w1 + w2 + w3;
        k += 4;
    }
    for (; k < end; k++) {
        int sl = 0; float wv = 0.f;
        if (lane == 0) {
            sl = __ldg(&g_ssrc[k]);
            wv = __expf(lrelu(__ldg(&g_el2[sl]) + er_n));
        }
        int s0 = __shfl_sync(0xffffffffu, sl, 0);
        float w0 = __shfl_sync(0xffffffffu, wv, 0);
        uint32_t r0 = __ldg((const uint32_t*)(g_feat2h + (size_t)s0 * F2) + lane);
        float2 f0 = __half22float2(*(__half2*)&r0);
        ax += w0 * f0.x; ay += w0 * f0.y;
        ws += w0;
    }
    float sv = (end > start) ? (1.f / ws) : 0.f;
    *(float2*)(out + (size_t)n * F2 + lane * 2) = make_float2(ax * sv, ay * sv);
}

// ---------------- launch ----------------
extern "C" void kernel_launch(void* const* d_in, const int* in_sizes, int n_in,
                              void* d_out, int out_size) {
    const float* x   = (const float*)d_in[0];
    const float* W1  = (const float*)d_in[1];
    const float* al1 = (const float*)d_in[2];
    const float* ar1 = (const float*)d_in[3];
    const float* W2  = (const float*)d_in[4];
    const float* al2 = (const float*)d_in[5];
    const float* ar2 = (const float*)d_in[6];
    const void*  src = d_in[7];
    const void*  dst = d_in[8];
    float* out = (float*)d_out;

    const int WB = (NN + 7) / 8;                // 12500
    const int MTILES = (NN + 127) / 128;        // 782

    // 1: detect + zero deg / el2 / er2
    k_setup0<<<1 + (NN + 255) / 256, 256>>>((const long long*)src);
    // 2: conv || cast || v-vector precompute
    k_setup1<<<EBLK * 2 + 8, 256>>>((const float4*)x, (const float4*)W1, (const float4*)W2,
                                    src, dst, al1, ar1);
    // 3: rowptr scan
    k_scan<<<1, 1024>>>();
    // 4: CSR scatter (src + dst)
    k_scatter<<<EBLK, 256>>>();
    // 5: layer1 scores from v-vectors
    k_score1<<<WB, 256>>>();
    // 6: edge weights (CSR order, streaming)
    k_wgt<<<EBLK, 256>>>();
    // 7: aggregate x — pure gather loop, no dep chain
    k_aggx<<<WB, 256>>>();
    // 8: h1 = ELU(aggx @ W1) — 4 batched 128-wide GEMMs
    k_gemmelu<<<dim3(2, MTILES, 4), 256>>>();
    // 9: feat2 = h1 @ W2 + fused scores
    k_gemm2h<<<dim3(1, MTILES), 256>>>(al2, ar2);
    // 10: layer2 aggregation -> out
    k_agg2<<<WB, 256>>>(out);
}

// round 14
// speedup vs baseline: 1.2217x; 1.0358x over previous
#include <cuda_runtime.h>
#include <cuda_fp16.h>
#include <math.h>
#include <stdint.h>

// Problem constants (fixed by the reference)
#define NN 100000
#define NE 3200000
#define H1 4
#define D1 128
#define F1 512     // H1*D1
#define F2 64
#define NEG_SLOPE 0.2f

// ---------------- scratch (static __device__ arrays; allocation is forbidden) ----------------
__device__ __align__(16) __half g_xh[(size_t)NN * D1];      // x in fp16 (25.6 MB, L2-resident gather table)
__device__ __align__(16) __half g_w1h[D1 * F1];             // W1 fp16
__device__ __align__(16) __half g_w2h[F1 * F2];             // W2 fp16
__device__ __align__(16) __half g_aggx[(size_t)NN * F1];    // (Σ w·x)/S per (node,head): [N][H*128] fp16
__device__ __align__(16) __half g_h1h[(size_t)NN * F1];     // ELU(aggx@W1) fp16, node-major [N][512]
__device__ __align__(16) __half g_feat2h[(size_t)NN * F2];  // layer2 linear out fp16 (12.8 MB)
__device__ __align__(16) float g_vl[F1], g_vr[F1];          // W1_h @ al_h / ar_h, [h*128+i]
__device__ __align__(16) float4 g_els[NN];                  // el1 per node, 4 heads
__device__ __align__(16) float4 g_ers[NN];                  // er1 per node, 4 heads
__device__ __align__(16) float4 g_w4[NE];                   // layer1 edge weights, CSR order (51.2 MB)
__device__ __align__(16) float g_w2e[NE];                   // layer2 edge weights, CSR order (12.8 MB)
__device__ float g_el2[NN], g_er2[NN];
__device__ int g_src32[NE], g_dst32[NE];   // int32 index mirrors
__device__ __align__(16) int g_ssrc[NE];   // src id per CSR slot
__device__ __align__(16) int g_sdst[NE];   // dst id per CSR slot
__device__ int g_deg[NN];
__device__ int g_rowptr[NN + 1];
__device__ int g_cursor[NN];
__device__ int g_mode;                     // 0 = int64 indices, 1 = int32 indices

// ---------------- helpers ----------------
__device__ __forceinline__ float lrelu(float x) { return x >= 0.f ? x : NEG_SLOPE * x; }

__device__ __forceinline__ void ldsm_x4(uint32_t r[4], uint32_t addr) {
    asm volatile("ldmatrix.sync.aligned.m8n8.x4.shared.b16 {%0,%1,%2,%3}, [%4];"
                 : "=r"(r[0]), "=r"(r[1]), "=r"(r[2]), "=r"(r[3]) : "r"(addr));
}
__device__ __forceinline__ void ldsm_x4_t(uint32_t r[4], uint32_t addr) {
    asm volatile("ldmatrix.sync.aligned.m8n8.x4.trans.shared.b16 {%0,%1,%2,%3}, [%4];"
                 : "=r"(r[0]), "=r"(r[1]), "=r"(r[2]), "=r"(r[3]) : "r"(addr));
}
__device__ __forceinline__ void mma16816(float c[4], const uint32_t a[4], const uint32_t b[2]) {
    asm volatile("mma.sync.aligned.m16n8k16.row.col.f32.f16.f16.f32 "
                 "{%0,%1,%2,%3}, {%4,%5,%6,%7}, {%8,%9}, {%0,%1,%2,%3};"
                 : "+f"(c[0]), "+f"(c[1]), "+f"(c[2]), "+f"(c[3])
                 : "r"(a[0]), "r"(a[1]), "r"(a[2]), "r"(a[3]), "r"(b[0]), "r"(b[1]));
}
__device__ __forceinline__ void cp16(uint32_t smem, const void* g) {
    asm volatile("cp.async.cg.shared.global [%0], [%1], 16;" :: "r"(smem), "l"(g));
}
__device__ __forceinline__ void cp_commit() { asm volatile("cp.async.commit_group;"); }
__device__ __forceinline__ void cp_wait1() { asm volatile("cp.async.wait_group 1;"); }
__device__ __forceinline__ void cp_wait0() { asm volatile("cp.async.wait_group 0;"); }

// ---------------- launch 1: detect index width + zero deg / layer2 score accumulators ------
__global__ void k_setup0(const long long* __restrict__ src) {
    if (blockIdx.x == 0) {
        if (threadIdx.x == 0) {
            int m = 0;
            for (int i = 0; i < 256; i++) {
                long long v = src[i];
                if (v < 0 || v >= NN) { m = 1; break; }
            }
            g_mode = m;
        }
        return;
    }
    int i = (blockIdx.x - 1) * blockDim.x + threadIdx.x;
    if (i < NN) { g_deg[i] = 0; g_el2[i] = 0.f; g_er2[i] = 0.f; }
}

// ---------------- launch 2: conv || cast || score-vector precompute ----------------
__device__ __forceinline__ uint2 f4toh(float4 v) {
    __half2 a = __floats2half2_rn(v.x, v.y);
    __half2 b = __floats2half2_rn(v.z, v.w);
    uint2 r;
    r.x = *(uint32_t*)&a;
    r.y = *(uint32_t*)&b;
    return r;
}
#define EBLK 12500
__global__ void k_setup1(const float4* __restrict__ x, const float4* __restrict__ w1,
                         const float4* __restrict__ w2,
                         const void* __restrict__ srcp, const void* __restrict__ dstp,
                         const float* __restrict__ al1, const float* __restrict__ ar1) {
    if (blockIdx.x < EBLK) {
        // conv: widen indices + degree histogram
        int i = blockIdx.x * blockDim.x + threadIdx.x;
        if (i >= NE) return;
        int s, d;
        if (g_mode) {
            s = ((const int*)srcp)[i];
            d = ((const int*)dstp)[i];
        } else {
            s = (int)((const long long*)srcp)[i];
            d = (int)((const long long*)dstp)[i];
        }
        g_src32[i] = s;
        g_dst32[i] = d;
        atomicAdd(&g_deg[d], 1);
    } else if (blockIdx.x < 2 * EBLK) {
        // cast x, W1, W2 to fp16
        int i = (blockIdx.x - EBLK) * blockDim.x + threadIdx.x;
        if (i < NN * D1 / 4) ((uint2*)g_xh)[i]  = f4toh(x[i]);
        if (i < D1 * F1 / 4) ((uint2*)g_w1h)[i] = f4toh(w1[i]);
        if (i < F1 * F2 / 4) ((uint2*)g_w2h)[i] = f4toh(w2[i]);
    } else {
        // v-vectors: block b in [0,8): h = b&3, r-side = b>>2
        int b = blockIdx.x - 2 * EBLK;      // 0..7
        int h = b & 3;
        const float* W1f = (const float*)w1;
        const float* a = (b >> 2) ? ar1 : al1;
        float* v = (b >> 2) ? g_vr : g_vl;
        int i = threadIdx.x;                // 0..255, need 0..127
        if (i < 128) {
            float sum = 0.f;
            #pragma unroll 4
            for (int d = 0; d < 128; d++)
                sum += W1f[i * F1 + h * 128 + d] * a[h * 128 + d];
            v[h * 128 + i] = sum;
        }
    }
}

// ---------------- launch 3: parallel exclusive scan of degrees ----------------
__global__ __launch_bounds__(1024) void k_scan() {
    const int PER = (NN + 1023) / 1024;  // 98
    int tid = threadIdx.x, lane = tid & 31, wid = tid >> 5;
    int base = tid * PER;
    int sum = 0;
    for (int j = 0; j < PER; j++) {
        int i = base + j;
        if (i < NN) sum += g_deg[i];
    }
    int incl = sum;
    #pragma unroll
    for (int o = 1; o < 32; o <<= 1) {
        int t = __shfl_up_sync(0xffffffffu, incl, o);
        if (lane >= o) incl += t;
    }
    __shared__ int wsum[32];
    if (lane == 31) wsum[wid] = incl;
    __syncthreads();
    if (wid == 0) {
        int v = wsum[lane];
        int z = v;
        #pragma unroll
        for (int o = 1; o < 32; o <<= 1) {
            int t = __shfl_up_sync(0xffffffffu, z, o);
            if (lane >= o) z += t;
        }
        wsum[lane] = z - v;
    }
    __syncthreads();
    int run = incl - sum + wsum[wid];
    for (int j = 0; j < PER; j++) {
        int i = base + j;
        if (i < NN) {
            g_rowptr[i] = run;
            g_cursor[i] = run;
            run += g_deg[i];
        }
    }
    if (tid == 1023) g_rowptr[NN] = run;
}

// ---------------- launch 4: CSR scatter (src + dst per slot) ----------------
__global__ void k_scatter() {
    int i = blockIdx.x * blockDim.x + threadIdx.x;
    if (i >= NE) return;
    int d = g_dst32[i];
    int pos = atomicAdd(&g_cursor[d], 1);
    g_ssrc[pos] = g_src32[i];
    g_sdst[pos] = d;
}

// ---------------- launch 5: layer1 scores via precomputed v-vectors ----------------
// el[n,h] = x[n]·vl[h];  er[n,h] = x[n]·vr[h].  Warp per node.
__global__ __launch_bounds__(256) void k_score1() {
    int w = (blockIdx.x * blockDim.x + threadIdx.x) >> 5;
    int lane = threadIdx.x & 31;
    if (w >= NN) return;
    uint2 xv = __ldg((const uint2*)(g_xh + (size_t)w * D1) + lane);
    __half2* p = (__half2*)&xv;
    float2 xa = __half22float2(p[0]);
    float2 xb = __half22float2(p[1]);
    float el[4], er[4];
    #pragma unroll
    for (int h = 0; h < 4; h++) {
        float4 vl = *(const float4*)&g_vl[h * 128 + lane * 4];
        float4 vr = *(const float4*)&g_vr[h * 128 + lane * 4];
        el[h] = xa.x * vl.x + xa.y * vl.y + xb.x * vl.z + xb.y * vl.w;
        er[h] = xa.x * vr.x + xa.y * vr.y + xb.x * vr.z + xb.y * vr.w;
    }
    #pragma unroll
    for (int o = 16; o > 0; o >>= 1) {
        #pragma unroll
        for (int h = 0; h < 4; h++) {
            el[h] += __shfl_xor_sync(0xffffffffu, el[h], o);
            er[h] += __shfl_xor_sync(0xffffffffu, er[h], o);
        }
    }
    if (lane == 0) {
        g_els[w] = make_float4(el[0], el[1], el[2], el[3]);
        g_ers[w] = make_float4(er[0], er[1], er[2], er[3]);
    }
}

// ---------------- launch 6: layer1 edge weights, CSR order, edge-parallel ----------------
__global__ void k_wgt() {
    int i = blockIdx.x * blockDim.x + threadIdx.x;
    if (i >= NE) return;
    int s = g_ssrc[i];
    int d = g_sdst[i];
    float4 e = __ldg(&g_els[s]);
    float4 r = __ldg(&g_ers[d]);
    float4 w;
    w.x = __expf(lrelu(e.x + r.x));
    w.y = __expf(lrelu(e.y + r.y));
    w.z = __expf(lrelu(e.z + r.z));
    w.w = __expf(lrelu(e.w + r.w));
    g_w4[i] = w;
}

// ---------------- launch 7: aggregate x with precomputed weights ----------------
// Warp per node; 8-edge batches; indices/weights via vector loads after a 16B-align
// peel; gathers issued back-to-back (MLP=8); NO shfl, NO exp in the loop.
__device__ __forceinline__ void accum_x(float4 w, uint2 r, float4 ac[4], float ws[4]) {
    __half2* p = (__half2*)&r;
    float2 fa = __half22float2(p[0]);
    float2 fb = __half22float2(p[1]);
    ac[0].x += w.x * fa.x; ac[0].y += w.x * fa.y; ac[0].z += w.x * fb.x; ac[0].w += w.x * fb.y;
    ac[1].x += w.y * fa.x; ac[1].y += w.y * fa.y; ac[1].z += w.y * fb.x; ac[1].w += w.y * fb.y;
    ac[2].x += w.z * fa.x; ac[2].y += w.z * fa.y; ac[2].z += w.z * fb.x; ac[2].w += w.z * fb.y;
    ac[3].x += w.w * fa.x; ac[3].y += w.w * fa.y; ac[3].z += w.w * fb.x; ac[3].w += w.w * fb.y;
    ws[0] += w.x; ws[1] += w.y; ws[2] += w.z; ws[3] += w.w;
}
__global__ __launch_bounds__(256) void k_aggx() {
    int n = blockIdx.x * 8 + (threadIdx.x >> 5);
    int lane = threadIdx.x & 31;
    if (n >= NN) return;
    int start = g_rowptr[n], end = g_rowptr[n + 1];
    float4 ac[4] = {{0,0,0,0},{0,0,0,0},{0,0,0,0},{0,0,0,0}};
    float ws[4] = {0,0,0,0};
    int k = start;
    // peel to 4-edge (16B) alignment
    for (; k < end && (k & 3); k++) {
        int s0 = __ldg(&g_ssrc[k]);
        uint2 r0 = __ldg((const uint2*)(g_xh + (size_t)s0 * D1) + lane);
        accum_x(__ldg(&g_w4[k]), r0, ac, ws);
    }
    for (; k + 7 < end; k += 8) {
        int4 sa = __ldg((const int4*)(g_ssrc + k));
        int4 sb = __ldg((const int4*)(g_ssrc + k + 4));
        uint2 r0 = __ldg((const uint2*)(g_xh + (size_t)sa.x * D1) + lane);
        uint2 r1 = __ldg((const uint2*)(g_xh + (size_t)sa.y * D1) + lane);
        uint2 r2 = __ldg((const uint2*)(g_xh + (size_t)sa.z * D1) + lane);
        uint2 r3 = __ldg((const uint2*)(g_xh + (size_t)sa.w * D1) + lane);
        uint2 r4 = __ldg((const uint2*)(g_xh + (size_t)sb.x * D1) + lane);
        uint2 r5 = __ldg((const uint2*)(g_xh + (size_t)sb.y * D1) + lane);
        uint2 r6 = __ldg((const uint2*)(g_xh + (size_t)sb.z * D1) + lane);
        uint2 r7 = __ldg((const uint2*)(g_xh + (size_t)sb.w * D1) + lane);
        accum_x(__ldg(&g_w4[k + 0]), r0, ac, ws);
        accum_x(__ldg(&g_w4[k + 1]), r1, ac, ws);
        accum_x(__ldg(&g_w4[k + 2]), r2, ac, ws);
        accum_x(__ldg(&g_w4[k + 3]), r3, ac, ws);
        accum_x(__ldg(&g_w4[k + 4]), r4, ac, ws);
        accum_x(__ldg(&g_w4[k + 5]), r5, ac, ws);
        accum_x(__ldg(&g_w4[k + 6]), r6, ac, ws);
        accum_x(__ldg(&g_w4[k + 7]), r7, ac, ws);
    }
    if (k + 3 < end) {
        int4 sa = __ldg((const int4*)(g_ssrc + k));
        uint2 r0 = __ldg((const uint2*)(g_xh + (size_t)sa.x * D1) + lane);
        uint2 r1 = __ldg((const uint2*)(g_xh + (size_t)sa.y * D1) + lane);
        uint2 r2 = __ldg((const uint2*)(g_xh + (size_t)sa.z * D1) + lane);
        uint2 r3 = __ldg((const uint2*)(g_xh + (size_t)sa.w * D1) + lane);
        accum_x(__ldg(&g_w4[k + 0]), r0, ac, ws);
        accum_x(__ldg(&g_w4[k + 1]), r1, ac, ws);
        accum_x(__ldg(&g_w4[k + 2]), r2, ac, ws);
        accum_x(__ldg(&g_w4[k + 3]), r3, ac, ws);
        k += 4;
    }
    for (; k < end; k++) {
        int s0 = __ldg(&g_ssrc[k]);
        uint2 r0 = __ldg((const uint2*)(g_xh + (size_t)s0 * D1) + lane);
        accum_x(__ldg(&g_w4[k]), r0, ac, ws);
    }
    bool has = end > start;
    __half* O = g_aggx + (size_t)n * F1 + lane * 4;
    #pragma unroll
    for (int h = 0; h < 4; h++) {
        float iv = has ? (1.f / ws[h]) : 0.f;
        __half2 h0 = __floats2half2_rn(ac[h].x * iv, ac[h].y * iv);
        __half2 h1 = __floats2half2_rn(ac[h].z * iv, ac[h].w * iv);
        *(uint2*)(O + h * 128) = make_uint2(*(uint32_t*)&h0, *(uint32_t*)&h1);
    }
}

// ---------------- HMMA fp16 GEMM, cp.async double-buffered, strided operands ----------
// BM=128, BN=64, BK=32; 8 warps (4m x 2n), 32x32 per warp.
// OUTMODE 2: plain fp16 store + fused el2/er2 score atomics (layer-2 GEMM)
// OUTMODE 3: ELU applied, fp16 store, no scores (layer-1 aggx@W1)
template<int K, int OUTMODE>
__device__ __forceinline__ void gemm_body(const __half* __restrict__ A, int lda,
                                          const __half* __restrict__ B, int ldb,
                                          __half* __restrict__ Ch, int ldc, int M,
                                          const float* __restrict__ al,
                                          const float* __restrict__ ar,
                                          int rowBase, int colBase) {
    __shared__ __half As[2][128][40];  // +8 pad
    __shared__ __half Bs[2][32][72];   // +8 pad
    int tid = threadIdx.x;
    int lane = tid & 31, wid = tid >> 5;
    int wm = wid >> 1, wn = wid & 1;

    float acc[2][4][4];
    #pragma unroll
    for (int a = 0; a < 2; a++)
        #pragma unroll
        for (int b = 0; b < 4; b++)
            #pragma unroll
            for (int c = 0; c < 4; c++) acc[a][b][c] = 0.f;

    uint32_t as_base = (uint32_t)__cvta_generic_to_shared(&As[0][0][0]);
    uint32_t bs_base = (uint32_t)__cvta_generic_to_shared(&Bs[0][0][0]);

    auto load_tiles = [&](int kt, int b) {
        #pragma unroll
        for (int hh = 0; hh < 2; hh++) {
            int r = (tid >> 2) + hh * 64;
            int grow = rowBase + r;
            if (grow >= M) grow = M - 1;
            cp16(as_base + (uint32_t)(((b << 7) + r) * 40 + (tid & 3) * 8) * 2,
                 A + (size_t)grow * lda + kt + (tid & 3) * 8);
        }
        int r = tid >> 3, c = (tid & 7) * 8;
        cp16(bs_base + (uint32_t)(((b << 5) + r) * 72 + c) * 2,
             B + (size_t)(kt + r) * ldb + colBase + c);
    };

    int g = lane >> 3;
    int arow_l = (lane & 7) + ((g & 1) ? 8 : 0);
    int acol_l = (g & 2) ? 8 : 0;
    int brow_l = ((g & 1) ? 8 : 0) + (lane & 7);
    int bcol_l = (g & 2) ? 8 : 0;

    const int NIT = K / 32;
    load_tiles(0, 0);
    cp_commit();
    int buf = 0;
    for (int it = 0; it < NIT; it++) {
        if (it + 1 < NIT) {
            load_tiles((it + 1) * 32, buf ^ 1);
            cp_commit();
            cp_wait1();
        } else {
            cp_wait0();
        }
        __syncthreads();
        #pragma unroll
        for (int kk = 0; kk < 2; kk++) {
            uint32_t af[2][4], bf[4][2];
            #pragma unroll
            for (int mi = 0; mi < 2; mi++) {
                int arow = wm * 32 + mi * 16 + arow_l;
                int acol = kk * 16 + acol_l;
                ldsm_x4(af[mi], as_base + (uint32_t)(((buf << 7) + arow) * 40 + acol) * 2);
            }
            #pragma unroll
            for (int n2 = 0; n2 < 2; n2++) {
                int kr = kk * 16 + brow_l;
                int nc = wn * 32 + n2 * 16 + bcol_l;
                uint32_t r4[4];
                ldsm_x4_t(r4, bs_base + (uint32_t)(((buf << 5) + kr) * 72 + nc) * 2);
                bf[n2 * 2][0] = r4[0]; bf[n2 * 2][1] = r4[1];
                bf[n2 * 2 + 1][0] = r4[2]; bf[n2 * 2 + 1][1] = r4[3];
            }
            #pragma unroll
            for (int mi = 0; mi < 2; mi++)
                #pragma unroll
                for (int nf = 0; nf < 4; nf++)
                    mma16816(acc[mi][nf], af[mi], bf[nf]);
        }
        __syncthreads();
        buf ^= 1;
    }

    int lr = lane >> 2, lc = (lane & 3) * 2;

    if constexpr (OUTMODE == 3) {
        // ELU + store
        #pragma unroll
        for (int mi = 0; mi < 2; mi++) {
            #pragma unroll
            for (int nf = 0; nf < 4; nf++) {
                int r0 = rowBase + wm * 32 + mi * 16 + lr;
                int cc = colBase + wn * 32 + nf * 8 + lc;
                float v0 = acc[mi][nf][0], v1 = acc[mi][nf][1];
                float v2 = acc[mi][nf][2], v3 = acc[mi][nf][3];
                v0 = v0 > 0.f ? v0 : expm1f(v0);
                v1 = v1 > 0.f ? v1 : expm1f(v1);
                v2 = v2 > 0.f ? v2 : expm1f(v2);
                v3 = v3 > 0.f ? v3 : expm1f(v3);
                if (r0 < M)
                    *(__half2*)(Ch + (size_t)r0 * ldc + cc) = __floats2half2_rn(v0, v1);
                if (r0 + 8 < M)
                    *(__half2*)(Ch + (size_t)(r0 + 8) * ldc + cc) = __floats2half2_rn(v2, v3);
            }
        }
    } else {
        // store + fused el2/er2 score epilogue
        float sel[4] = {0.f, 0.f, 0.f, 0.f};
        float ser[4] = {0.f, 0.f, 0.f, 0.f};
        #pragma unroll
        for (int mi = 0; mi < 2; mi++) {
            #pragma unroll
            for (int nf = 0; nf < 4; nf++) {
                int r0 = rowBase + wm * 32 + mi * 16 + lr;
                int cc = colBase + wn * 32 + nf * 8 + lc;
                float a0 = __ldg(&al[cc]),  a1 = __ldg(&al[cc + 1]);
                float r0a = __ldg(&ar[cc]), r1a = __ldg(&ar[cc + 1]);
                if (r0 < M)
                    *(__half2*)(Ch + (size_t)r0 * ldc + cc) =
                        __floats2half2_rn(acc[mi][nf][0], acc[mi][nf][1]);
                if (r0 + 8 < M)
                    *(__half2*)(Ch + (size_t)(r0 + 8) * ldc + cc) =
                        __floats2half2_rn(acc[mi][nf][2], acc[mi][nf][3]);
                sel[mi * 2]     += acc[mi][nf][0] * a0  + acc[mi][nf][1] * a1;
                sel[mi * 2 + 1] += acc[mi][nf][2] * a0  + acc[mi][nf][3] * a1;
                ser[mi * 2]     += acc[mi][nf][0] * r0a + acc[mi][nf][1] * r1a;
                ser[mi * 2 + 1] += acc[mi][nf][2] * r0a + acc[mi][nf][3] * r1a;
            }
        }
        #pragma unroll
        for (int q = 0; q < 4; q++) {
            sel[q] += __shfl_xor_sync(0xffffffffu, sel[q], 1);
            sel[q] += __shfl_xor_sync(0xffffffffu, sel[q], 2);
            ser[q] += __shfl_xor_sync(0xffffffffu, ser[q], 1);
            ser[q] += __shfl_xor_sync(0xffffffffu, ser[q], 2);
        }
        if ((lane & 3) == 0) {
            #pragma unroll
            for (int q = 0; q < 4; q++) {
                int r = rowBase + wm * 32 + (q >> 1) * 16 + (q & 1) * 8 + lr;
                if (r < M) {
                    atomicAdd(&g_el2[r], sel[q]);
                    atomicAdd(&g_er2[r], ser[q]);
                }
            }
        }
    }
}

// ---------------- launch 8: h1 = ELU(aggx_h @ W1_h), 4 batched GEMMs ----------------
__global__ __launch_bounds__(256) void k_gemmelu() {
    int h = blockIdx.z;
    gemm_body<128, 3>(g_aggx + h * 128, F1, g_w1h + h * 128, F1,
                      g_h1h + h * 128, F1, NN, nullptr, nullptr,
                      blockIdx.y * 128, blockIdx.x * 64);
}

// ---------------- launch 9: feat2 = h1 @ W2, fused el2/er2 scores ----------------
__global__ __launch_bounds__(256) void k_gemm2h(const float* __restrict__ al,
                                                const float* __restrict__ ar) {
    gemm_body<512, 2>(g_h1h, F1, g_w2h, F2, g_feat2h, F2, NN, al, ar,
                      blockIdx.y * 128, 0);
}

// ---------------- launch 10: layer2 edge weights, CSR order ----------------
__global__ void k_wgt2() {
    int i = blockIdx.x * blockDim.x + threadIdx.x;
    if (i >= NE) return;
    int s = g_ssrc[i];
    int d = g_sdst[i];
    g_w2e[i] = __expf(lrelu(__ldg(&g_el2[s]) + __ldg(&g_er2[d])));
}

// ---------------- launch 11: layer2 aggregation, pure gather -> d_out ----------------
__global__ __launch_bounds__(256) void k_agg2(float* __restrict__ out) {
    int n = blockIdx.x * 8 + (threadIdx.x >> 5);
    int lane = threadIdx.x & 31;
    if (n >= NN) return;
    int start = g_rowptr[n], end = g_rowptr[n + 1];
    float ax = 0.f, ay = 0.f, ws = 0.f;
    int k = start;
    // peel to 16B alignment
    for (; k < end && (k & 3); k++) {
        int s = __ldg(&g_ssrc[k]);
        float w = __ldg(&g_w2e[k]);
        uint32_t r = __ldg((const uint32_t*)(g_feat2h + (size_t)s * F2) + lane);
        float2 f = __half22float2(*(__half2*)&r);
        ax += w * f.x; ay += w * f.y; ws += w;
    }
    for (; k + 7 < end; k += 8) {
        int4 sa = __ldg((const int4*)(g_ssrc + k));
        int4 sb = __ldg((const int4*)(g_ssrc + k + 4));
        float4 wa = __ldg((const float4*)(g_w2e + k));
        float4 wb = __ldg((const float4*)(g_w2e + k + 4));
        uint32_t r0 = __ldg((const uint32_t*)(g_feat2h + (size_t)sa.x * F2) + lane);
        uint32_t r1 = __ldg((const uint32_t*)(g_feat2h + (size_t)sa.y * F2) + lane);
        uint32_t r2 = __ldg((const uint32_t*)(g_feat2h + (size_t)sa.z * F2) + lane);
        uint32_t r3 = __ldg((const uint32_t*)(g_feat2h + (size_t)sa.w * F2) + lane);
        uint32_t r4 = __ldg((const uint32_t*)(g_feat2h + (size_t)sb.x * F2) + lane);
        uint32_t r5 = __ldg((const uint32_t*)(g_feat2h + (size_t)sb.y * F2) + lane);
        uint32_t r6 = __ldg((const uint32_t*)(g_feat2h + (size_t)sb.z * F2) + lane);
        uint32_t r7 = __ldg((const uint32_t*)(g_feat2h + (size_t)sb.w * F2) + lane);
        float2 f;
        f = __half22float2(*(__half2*)&r0); ax += wa.x * f.x; ay += wa.x * f.y;
        f = __half22float2(*(__half2*)&r1); ax += wa.y * f.x; ay += wa.y * f.y;
        f = __half22float2(*(__half2*)&r2); ax += wa.z * f.x; ay += wa.z * f.y;
        f = __half22float2(*(__half2*)&r3); ax += wa.w * f.x; ay += wa.w * f.y;
        f = __half22float2(*(__half2*)&r4); ax += wb.x * f.x; ay += wb.x * f.y;
        f = __half22float2(*(__half2*)&r5); ax += wb.y * f.x; ay += wb.y * f.y;
        f = __half22float2(*(__half2*)&r6); ax += wb.z * f.x; ay += wb.z * f.y;
        f = __half22float2(*(__half2*)&r7); ax += wb.w * f.x; ay += wb.w * f.y;
        ws += wa.x + wa.y + wa.z + wa.w + wb.x + wb.y + wb.z + wb.w;
    }
    if (k + 3 < end) {
        int4 sa = __ldg((const int4*)(g_ssrc + k));
        float4 wa = __ldg((const float4*)(g_w2e + k));
        uint32_t r0 = __ldg((const uint32_t*)(g_feat2h + (size_t)sa.x * F2) + lane);
        uint32_t r1 = __ldg((const uint32_t*)(g_feat2h + (size_t)sa.y * F2) + lane);
        uint32_t r2 = __ldg((const uint32_t*)(g_feat2h + (size_t)sa.z * F2) + lane);
        uint32_t r3 = __ldg((const uint32_t*)(g_feat2h + (size_t)sa.w * F2) + lane);
        float2 f;
        f = __half22float2(*(__half2*)&r0); ax += wa.x * f.x; ay += wa.x * f.y;
        f = __half22float2(*(__half2*)&r1); ax += wa.y * f.x; ay += wa.y * f.y;
        f = __half22float2(*(__half2*)&r2); ax += wa.z * f.x; ay += wa.z * f.y;
        f = __half22float2(*(__half2*)&r3); ax += wa.w * f.x; ay += wa.w * f.y;
        ws += wa.x + wa.y + wa.z + wa.w;
        k += 4;
    }
    for (; k < end; k++) {
        int s = __ldg(&g_ssrc[k]);
        float w = __ldg(&g_w2e[k]);
        uint32_t r = __ldg((const uint32_t*)(g_feat2h + (size_t)s * F2) + lane);
        float2 f = __half22float2(*(__half2*)&r);
        ax += w * f.x; ay += w * f.y; ws += w;
    }
    float sv = (end > start) ? (1.f / ws) : 0.f;
    *(float2*)(out + (size_t)n * F2 + lane * 2) = make_float2(ax * sv, ay * sv);
}

// ---------------- launch ----------------
extern "C" void kernel_launch(void* const* d_in, const int* in_sizes, int n_in,
                              void* d_out, int out_size) {
    const float* x   = (const float*)d_in[0];
    const float* W1  = (const float*)d_in[1];
    const float* al1 = (const float*)d_in[2];
    const float* ar1 = (const float*)d_in[3];
    const float* W2  = (const float*)d_in[4];
    const float* al2 = (const float*)d_in[5];
    const float* ar2 = (const float*)d_in[6];
    const void*  src = d_in[7];
    const void*  dst = d_in[8];
    float* out = (float*)d_out;

    const int WB = (NN + 7) / 8;                // 12500
    const int MTILES = (NN + 127) / 128;        // 782

    // 1: detect + zero deg / el2 / er2
    k_setup0<<<1 + (NN + 255) / 256, 256>>>((const long long*)src);
    // 2: conv || cast || v-vector precompute
    k_setup1<<<EBLK * 2 + 8, 256>>>((const float4*)x, (const float4*)W1, (const float4*)W2,
                                    src, dst, al1, ar1);
    // 3: rowptr scan
    k_scan<<<1, 1024>>>();
    // 4: CSR scatter (src + dst)
    k_scatter<<<EBLK, 256>>>();
    // 5: layer1 scores from v-vectors
    k_score1<<<WB, 256>>>();
    // 6: layer1 edge weights (CSR order, streaming)
    k_wgt<<<EBLK, 256>>>();
    // 7: aggregate x — pure gather loop
    k_aggx<<<WB, 256>>>();
    // 8: h1 = ELU(aggx @ W1) — 4 batched 128-wide GEMMs
    k_gemmelu<<<dim3(2, MTILES, 4), 256>>>();
    // 9: feat2 = h1 @ W2 + fused scores
    k_gemm2h<<<dim3(1, MTILES), 256>>>(al2, ar2);
    // 10: layer2 edge weights (CSR order, streaming)
    k_wgt2<<<EBLK, 256>>>();
    // 11: layer2 aggregation — pure gather -> out
    k_agg2<<<WB, 256>>>(out);
}

// round 15
// speedup vs baseline: 1.2718x; 1.0411x over previous
#include <cuda_runtime.h>
#include <cuda_fp16.h>
#include <math.h>
#include <stdint.h>

// Problem constants (fixed by the reference)
#define NN 100000
#define NE 3200000
#define H1 4
#define D1 128
#define F1 512     // H1*D1
#define F2 64
#define NEG_SLOPE 0.2f

// ---------------- scratch (static __device__ arrays; allocation is forbidden) ----------------
__device__ __align__(16) __half g_xh[(size_t)NN * D1];      // x in fp16 (25.6 MB, L2-resident gather table)
__device__ __align__(16) __half g_w1h[D1 * F1];             // W1 fp16
__device__ __align__(16) __half g_w2h[F1 * F2];             // W2 fp16
__device__ __align__(16) __half g_aggx[(size_t)NN * F1];    // (Σ w·x)/S per (node,head): [N][H*128] fp16
__device__ __align__(16) __half g_h1h[(size_t)NN * F1];     // ELU(aggx@W1) fp16, node-major [N][512]
__device__ __align__(16) __half g_feat2h[(size_t)NN * F2];  // layer2 linear out fp16 (12.8 MB)
__device__ __align__(16) float g_vl[F1], g_vr[F1];          // W1_h @ al_h / ar_h, [h*128+i]
__device__ __align__(16) float4 g_els[NN];                  // el1 per node, 4 heads
__device__ __align__(16) float4 g_ers[NN];                  // er1 per node, 4 heads
__device__ __align__(16) uint4 g_w4h[NE];                   // layer1 edge weights as 4x broadcast half2 (51.2 MB)
__device__ __align__(16) float4 g_iws1[NN];                 // 1/Σw per (node,head)
__device__ __align__(16) float g_w2e[NE];                   // layer2 edge weights, CSR order (12.8 MB)
__device__ float g_iws2[NN];                                // 1/Σw2 per node
__device__ float g_el2[NN], g_er2[NN];
__device__ int g_src32[NE], g_dst32[NE];   // int32 index mirrors
__device__ __align__(16) int g_ssrc[NE];   // src id per CSR slot
__device__ int g_deg[NN];
__device__ int g_rowptr[NN + 1];
__device__ int g_cursor[NN];
__device__ int g_mode;                     // 0 = int64 indices, 1 = int32 indices

// ---------------- helpers ----------------
__device__ __forceinline__ float lrelu(float x) { return x >= 0.f ? x : NEG_SLOPE * x; }

__device__ __forceinline__ void ldsm_x4(uint32_t r[4], uint32_t addr) {
    asm volatile("ldmatrix.sync.aligned.m8n8.x4.shared.b16 {%0,%1,%2,%3}, [%4];"
                 : "=r"(r[0]), "=r"(r[1]), "=r"(r[2]), "=r"(r[3]) : "r"(addr));
}
__device__ __forceinline__ void ldsm_x4_t(uint32_t r[4], uint32_t addr) {
    asm volatile("ldmatrix.sync.aligned.m8n8.x4.trans.shared.b16 {%0,%1,%2,%3}, [%4];"
                 : "=r"(r[0]), "=r"(r[1]), "=r"(r[2]), "=r"(r[3]) : "r"(addr));
}
__device__ __forceinline__ void mma16816(float c[4], const uint32_t a[4], const uint32_t b[2]) {
    asm volatile("mma.sync.aligned.m16n8k16.row.col.f32.f16.f16.f32 "
                 "{%0,%1,%2,%3}, {%4,%5,%6,%7}, {%8,%9}, {%0,%1,%2,%3};"
                 : "+f"(c[0]), "+f"(c[1]), "+f"(c[2]), "+f"(c[3])
                 : "r"(a[0]), "r"(a[1]), "r"(a[2]), "r"(a[3]), "r"(b[0]), "r"(b[1]));
}
__device__ __forceinline__ void cp16(uint32_t smem, const void* g) {
    asm volatile("cp.async.cg.shared.global [%0], [%1], 16;" :: "r"(smem), "l"(g));
}
__device__ __forceinline__ void cp_commit() { asm volatile("cp.async.commit_group;"); }
__device__ __forceinline__ void cp_wait1() { asm volatile("cp.async.wait_group 1;"); }
__device__ __forceinline__ void cp_wait0() { asm volatile("cp.async.wait_group 0;"); }

// ---------------- launch 1: detect index width + zero deg / layer2 score accumulators ------
__global__ void k_setup0(const long long* __restrict__ src) {
    if (blockIdx.x == 0) {
        if (threadIdx.x == 0) {
            int m = 0;
            for (int i = 0; i < 256; i++) {
                long long v = src[i];
                if (v < 0 || v >= NN) { m = 1; break; }
            }
            g_mode = m;
        }
        return;
    }
    int i = (blockIdx.x - 1) * blockDim.x + threadIdx.x;
    if (i < NN) { g_deg[i] = 0; g_el2[i] = 0.f; g_er2[i] = 0.f; }
}

// ---------------- launch 2: conv || cast || score-vector precompute ----------------
__device__ __forceinline__ uint2 f4toh(float4 v) {
    __half2 a = __floats2half2_rn(v.x, v.y);
    __half2 b = __floats2half2_rn(v.z, v.w);
    uint2 r;
    r.x = *(uint32_t*)&a;
    r.y = *(uint32_t*)&b;
    return r;
}
#define EBLK 12500
__global__ void k_setup1(const float4* __restrict__ x, const float4* __restrict__ w1,
                         const float4* __restrict__ w2,
                         const void* __restrict__ srcp, const void* __restrict__ dstp,
                         const float* __restrict__ al1, const float* __restrict__ ar1) {
    if (blockIdx.x < EBLK) {
        // conv: widen indices + degree histogram
        int i = blockIdx.x * blockDim.x + threadIdx.x;
        if (i >= NE) return;
        int s, d;
        if (g_mode) {
            s = ((const int*)srcp)[i];
            d = ((const int*)dstp)[i];
        } else {
            s = (int)((const long long*)srcp)[i];
            d = (int)((const long long*)dstp)[i];
        }
        g_src32[i] = s;
        g_dst32[i] = d;
        atomicAdd(&g_deg[d], 1);
    } else if (blockIdx.x < 2 * EBLK) {
        // cast x, W1, W2 to fp16
        int i = (blockIdx.x - EBLK) * blockDim.x + threadIdx.x;
        if (i < NN * D1 / 4) ((uint2*)g_xh)[i]  = f4toh(x[i]);
        if (i < D1 * F1 / 4) ((uint2*)g_w1h)[i] = f4toh(w1[i]);
        if (i < F1 * F2 / 4) ((uint2*)g_w2h)[i] = f4toh(w2[i]);
    } else {
        // v-vectors: block b in [0,8): h = b&3, r-side = b>>2
        int b = blockIdx.x - 2 * EBLK;      // 0..7
        int h = b & 3;
        const float* W1f = (const float*)w1;
        const float* a = (b >> 2) ? ar1 : al1;
        float* v = (b >> 2) ? g_vr : g_vl;
        int i = threadIdx.x;                // 0..255, need 0..127
        if (i < 128) {
            float sum = 0.f;
            #pragma unroll 4
            for (int d = 0; d < 128; d++)
                sum += W1f[i * F1 + h * 128 + d] * a[h * 128 + d];
            v[h * 128 + i] = sum;
        }
    }
}

// ---------------- launch 3: parallel exclusive scan of degrees ----------------
__global__ __launch_bounds__(1024) void k_scan() {
    const int PER = (NN + 1023) / 1024;  // 98
    int tid = threadIdx.x, lane = tid & 31, wid = tid >> 5;
    int base = tid * PER;
    int sum = 0;
    for (int j = 0; j < PER; j++) {
        int i = base + j;
        if (i < NN) sum += g_deg[i];
    }
    int incl = sum;
    #pragma unroll
    for (int o = 1; o < 32; o <<= 1) {
        int t = __shfl_up_sync(0xffffffffu, incl, o);
        if (lane >= o) incl += t;
    }
    __shared__ int wsum[32];
    if (lane == 31) wsum[wid] = incl;
    __syncthreads();
    if (wid == 0) {
        int v = wsum[lane];
        int z = v;
        #pragma unroll
        for (int o = 1; o < 32; o <<= 1) {
            int t = __shfl_up_sync(0xffffffffu, z, o);
            if (lane >= o) z += t;
        }
        wsum[lane] = z - v;
    }
    __syncthreads();
    int run = incl - sum + wsum[wid];
    for (int j = 0; j < PER; j++) {
        int i = base + j;
        if (i < NN) {
            g_rowptr[i] = run;
            g_cursor[i] = run;
            run += g_deg[i];
        }
    }
    if (tid == 1023) g_rowptr[NN] = run;
}

// ---------------- launch 4: CSR scatter (src only; dst is implicit in row) ----------------
__global__ void k_scatter() {
    int i = blockIdx.x * blockDim.x + threadIdx.x;
    if (i >= NE) return;
    int d = g_dst32[i];
    int pos = atomicAdd(&g_cursor[d], 1);
    g_ssrc[pos] = g_src32[i];
}

// ---------------- launch 5: layer1 scores via precomputed v-vectors ----------------
// el[n,h] = x[n]·vl[h];  er[n,h] = x[n]·vr[h].  Warp per node.
__global__ __launch_bounds__(256) void k_score1() {
    int w = (blockIdx.x * blockDim.x + threadIdx.x) >> 5;
    int lane = threadIdx.x & 31;
    if (w >= NN) return;
    uint2 xv = __ldg((const uint2*)(g_xh + (size_t)w * D1) + lane);
    __half2* p = (__half2*)&xv;
    float2 xa = __half22float2(p[0]);
    float2 xb = __half22float2(p[1]);
    float el[4], er[4];
    #pragma unroll
    for (int h = 0; h < 4; h++) {
        float4 vl = *(const float4*)&g_vl[h * 128 + lane * 4];
        float4 vr = *(const float4*)&g_vr[h * 128 + lane * 4];
        el[h] = xa.x * vl.x + xa.y * vl.y + xb.x * vl.z + xb.y * vl.w;
        er[h] = xa.x * vr.x + xa.y * vr.y + xb.x * vr.z + xb.y * vr.w;
    }
    #pragma unroll
    for (int o = 16; o > 0; o >>= 1) {
        #pragma unroll
        for (int h = 0; h < 4; h++) {
            el[h] += __shfl_xor_sync(0xffffffffu, el[h], o);
            er[h] += __shfl_xor_sync(0xffffffffu, er[h], o);
        }
    }
    if (lane == 0) {
        g_els[w] = make_float4(el[0], el[1], el[2], el[3]);
        g_ers[w] = make_float4(er[0], er[1], er[2], er[3]);
    }
}

// ---------------- launch 6: layer1 edge weights (node-parallel, dst implicit) -------------
// Warp per node, lane per edge. Writes broadcast-half2 weight quads (coalesced) and the
// per-node 1/Σw (float4) via warp reduction. No g_sdst needed anywhere.
__global__ __launch_bounds__(256) void k_wgt() {
    int n = blockIdx.x * 8 + (threadIdx.x >> 5);
    int lane = threadIdx.x & 31;
    if (n >= NN) return;
    int start = g_rowptr[n], end = g_rowptr[n + 1];
    float4 er = g_ers[n];
    float ws0 = 0.f, ws1 = 0.f, ws2 = 0.f, ws3 = 0.f;
    for (int k = start + lane; k < end; k += 32) {
        int s = __ldg(&g_ssrc[k]);
        float4 e = __ldg(&g_els[s]);
        float w0 = __expf(lrelu(e.x + er.x));
        float w1 = __expf(lrelu(e.y + er.y));
        float w2 = __expf(lrelu(e.z + er.z));
        float w3 = __expf(lrelu(e.w + er.w));
        __half2 h0 = __half2half2(__float2half_rn(w0));
        __half2 h1 = __half2half2(__float2half_rn(w1));
        __half2 h2 = __half2half2(__float2half_rn(w2));
        __half2 h3 = __half2half2(__float2half_rn(w3));
        g_w4h[k] = make_uint4(*(uint32_t*)&h0, *(uint32_t*)&h1,
                              *(uint32_t*)&h2, *(uint32_t*)&h3);
        ws0 += w0; ws1 += w1; ws2 += w2; ws3 += w3;
    }
    #pragma unroll
    for (int o = 16; o > 0; o >>= 1) {
        ws0 += __shfl_xor_sync(0xffffffffu, ws0, o);
        ws1 += __shfl_xor_sync(0xffffffffu, ws1, o);
        ws2 += __shfl_xor_sync(0xffffffffu, ws2, o);
        ws3 += __shfl_xor_sync(0xffffffffu, ws3, o);
    }
    if (lane == 0) {
        bool has = end > start;
        g_iws1[n] = make_float4(has ? 1.f / ws0 : 0.f, has ? 1.f / ws1 : 0.f,
                                has ? 1.f / ws2 : 0.f, has ? 1.f / ws3 : 0.f);
    }
}

// ---------------- launch 7: aggregate x — HFMA2 inner loop, fp32 flush every 4 edges ------
__device__ __forceinline__ void accum_h(uint4 wq, uint2 r, __half2 hac[4][2]) {
    __half2* w = (__half2*)&wq;   // w[h] = (wh, wh)
    __half2* f = (__half2*)&r;
    #pragma unroll
    for (int h = 0; h < 4; h++) {
        hac[h][0] = __hfma2(w[h], f[0], hac[h][0]);
        hac[h][1] = __hfma2(w[h], f[1], hac[h][1]);
    }
}
__device__ __forceinline__ void flush_h(__half2 hac[4][2], float4 ac[4]) {
    #pragma unroll
    for (int h = 0; h < 4; h++) {
        float2 a = __half22float2(hac[h][0]);
        float2 b = __half22float2(hac[h][1]);
        ac[h].x += a.x; ac[h].y += a.y; ac[h].z += b.x; ac[h].w += b.y;
        hac[h][0] = __half2half2(__float2half_rn(0.f));
        hac[h][1] = hac[h][0];
    }
}
__global__ __launch_bounds__(256) void k_aggx() {
    int n = blockIdx.x * 8 + (threadIdx.x >> 5);
    int lane = threadIdx.x & 31;
    if (n >= NN) return;
    int start = g_rowptr[n], end = g_rowptr[n + 1];
    float4 ac[4] = {{0,0,0,0},{0,0,0,0},{0,0,0,0},{0,0,0,0}};
    __half2 hac[4][2];
    #pragma unroll
    for (int h = 0; h < 4; h++) hac[h][0] = hac[h][1] = __half2half2(__float2half_rn(0.f));
    int k = start;
    // peel to 4-edge (16B) alignment — fp32 path
    for (; k < end && (k & 3); k++) {
        int s0 = __ldg(&g_ssrc[k]);
        uint2 r0 = __ldg((const uint2*)(g_xh + (size_t)s0 * D1) + lane);
        accum_h(__ldg(&g_w4h[k]), r0, hac);
        flush_h(hac, ac);
    }
    for (; k + 7 < end; k += 8) {
        int4 sa = __ldg((const int4*)(g_ssrc + k));
        int4 sb = __ldg((const int4*)(g_ssrc + k + 4));
        uint2 r0 = __ldg((const uint2*)(g_xh + (size_t)sa.x * D1) + lane);
        uint2 r1 = __ldg((const uint2*)(g_xh + (size_t)sa.y * D1) + lane);
        uint2 r2 = __ldg((const uint2*)(g_xh + (size_t)sa.z * D1) + lane);
        uint2 r3 = __ldg((const uint2*)(g_xh + (size_t)sa.w * D1) + lane);
        uint2 r4 = __ldg((const uint2*)(g_xh + (size_t)sb.x * D1) + lane);
        uint2 r5 = __ldg((const uint2*)(g_xh + (size_t)sb.y * D1) + lane);
        uint2 r6 = __ldg((const uint2*)(g_xh + (size_t)sb.z * D1) + lane);
        uint2 r7 = __ldg((const uint2*)(g_xh + (size_t)sb.w * D1) + lane);
        accum_h(__ldg(&g_w4h[k + 0]), r0, hac);
        accum_h(__ldg(&g_w4h[k + 1]), r1, hac);
        accum_h(__ldg(&g_w4h[k + 2]), r2, hac);
        accum_h(__ldg(&g_w4h[k + 3]), r3, hac);
        flush_h(hac, ac);
        accum_h(__ldg(&g_w4h[k + 4]), r4, hac);
        accum_h(__ldg(&g_w4h[k + 5]), r5, hac);
        accum_h(__ldg(&g_w4h[k + 6]), r6, hac);
        accum_h(__ldg(&g_w4h[k + 7]), r7, hac);
        flush_h(hac, ac);
    }
    if (k + 3 < end) {
        int4 sa = __ldg((const int4*)(g_ssrc + k));
        uint2 r0 = __ldg((const uint2*)(g_xh + (size_t)sa.x * D1) + lane);
        uint2 r1 = __ldg((const uint2*)(g_xh + (size_t)sa.y * D1) + lane);
        uint2 r2 = __ldg((const uint2*)(g_xh + (size_t)sa.z * D1) + lane);
        uint2 r3 = __ldg((const uint2*)(g_xh + (size_t)sa.w * D1) + lane);
        accum_h(__ldg(&g_w4h[k + 0]), r0, hac);
        accum_h(__ldg(&g_w4h[k + 1]), r1, hac);
        accum_h(__ldg(&g_w4h[k + 2]), r2, hac);
        accum_h(__ldg(&g_w4h[k + 3]), r3, hac);
        flush_h(hac, ac);
        k += 4;
    }
    for (; k < end; k++) {
        int s0 = __ldg(&g_ssrc[k]);
        uint2 r0 = __ldg((const uint2*)(g_xh + (size_t)s0 * D1) + lane);
        accum_h(__ldg(&g_w4h[k]), r0, hac);
    }
    flush_h(hac, ac);
    float4 iv = g_iws1[n];
    __half* O = g_aggx + (size_t)n * F1 + lane * 4;
    {
        __half2 h0 = __floats2half2_rn(ac[0].x * iv.x, ac[0].y * iv.x);
        __half2 h1 = __floats2half2_rn(ac[0].z * iv.x, ac[0].w * iv.x);
        *(uint2*)(O + 0 * 128) = make_uint2(*(uint32_t*)&h0, *(uint32_t*)&h1);
    }
    {
        __half2 h0 = __floats2half2_rn(ac[1].x * iv.y, ac[1].y * iv.y);
        __half2 h1 = __floats2half2_rn(ac[1].z * iv.y, ac[1].w * iv.y);
        *(uint2*)(O + 1 * 128) = make_uint2(*(uint32_t*)&h0, *(uint32_t*)&h1);
    }
    {
        __half2 h0 = __floats2half2_rn(ac[2].x * iv.z, ac[2].y * iv.z);
        __half2 h1 = __floats2half2_rn(ac[2].z * iv.z, ac[2].w * iv.z);
        *(uint2*)(O + 2 * 128) = make_uint2(*(uint32_t*)&h0, *(uint32_t*)&h1);
    }
    {
        __half2 h0 = __floats2half2_rn(ac[3].x * iv.w, ac[3].y * iv.w);
        __half2 h1 = __floats2half2_rn(ac[3].z * iv.w, ac[3].w * iv.w);
        *(uint2*)(O + 3 * 128) = make_uint2(*(uint32_t*)&h0, *(uint32_t*)&h1);
    }
}

// ---------------- HMMA fp16 GEMM, cp.async double-buffered, strided operands ----------
// BM=128, BN=64, BK=32; 8 warps (4m x 2n), 32x32 per warp.
// OUTMODE 2: plain fp16 store + fused el2/er2 score atomics (layer-2 GEMM)
// OUTMODE 3: ELU applied, fp16 store, no scores (layer-1 aggx@W1)
template<int K, int OUTMODE>
__device__ __forceinline__ void gemm_body(const __half* __restrict__ A, int lda,
                                          const __half* __restrict__ B, int ldb,
                                          __half* __restrict__ Ch, int ldc, int M,
                                          const float* __restrict__ al,
                                          const float* __restrict__ ar,
                                          int rowBase, int colBase) {
    __shared__ __half As[2][128][40];  // +8 pad
    __shared__ __half Bs[2][32][72];   // +8 pad
    int tid = threadIdx.x;
    int lane = tid & 31, wid = tid >> 5;
    int wm = wid >> 1, wn = wid & 1;

    float acc[2][4][4];
    #pragma unroll
    for (int a = 0; a < 2; a++)
        #pragma unroll
        for (int b = 0; b < 4; b++)
            #pragma unroll
            for (int c = 0; c < 4; c++) acc[a][b][c] = 0.f;

    uint32_t as_base = (uint32_t)__cvta_generic_to_shared(&As[0][0][0]);
    uint32_t bs_base = (uint32_t)__cvta_generic_to_shared(&Bs[0][0][0]);

    auto load_tiles = [&](int kt, int b) {
        #pragma unroll
        for (int hh = 0; hh < 2; hh++) {
            int r = (tid >> 2) + hh * 64;
            int grow = rowBase + r;
            if (grow >= M) grow = M - 1;
            cp16(as_base + (uint32_t)(((b << 7) + r) * 40 + (tid & 3) * 8) * 2,
                 A + (size_t)grow * lda + kt + (tid & 3) * 8);
        }
        int r = tid >> 3, c = (tid & 7) * 8;
        cp16(bs_base + (uint32_t)(((b << 5) + r) * 72 + c) * 2,
             B + (size_t)(kt + r) * ldb + colBase + c);
    };

    int g = lane >> 3;
    int arow_l = (lane & 7) + ((g & 1) ? 8 : 0);
    int acol_l = (g & 2) ? 8 : 0;
    int brow_l = ((g & 1) ? 8 : 0) + (lane & 7);
    int bcol_l = (g & 2) ? 8 : 0;

    const int NIT = K / 32;
    load_tiles(0, 0);
    cp_commit();
    int buf = 0;
    for (int it = 0; it < NIT; it++) {
        if (it + 1 < NIT) {
            load_tiles((it + 1) * 32, buf ^ 1);
            cp_commit();
            cp_wait1();
        } else {
            cp_wait0();
        }
        __syncthreads();
        #pragma unroll
        for (int kk = 0; kk < 2; kk++) {
            uint32_t af[2][4], bf[4][2];
            #pragma unroll
            for (int mi = 0; mi < 2; mi++) {
                int arow = wm * 32 + mi * 16 + arow_l;
                int acol = kk * 16 + acol_l;
                ldsm_x4(af[mi], as_base + (uint32_t)(((buf << 7) + arow) * 40 + acol) * 2);
            }
            #pragma unroll
            for (int n2 = 0; n2 < 2; n2++) {
                int kr = kk * 16 + brow_l;
                int nc = wn * 32 + n2 * 16 + bcol_l;
                uint32_t r4[4];
                ldsm_x4_t(r4, bs_base + (uint32_t)(((buf << 5) + kr) * 72 + nc) * 2);
                bf[n2 * 2][0] = r4[0]; bf[n2 * 2][1] = r4[1];
                bf[n2 * 2 + 1][0] = r4[2]; bf[n2 * 2 + 1][1] = r4[3];
            }
            #pragma unroll
            for (int mi = 0; mi < 2; mi++)
                #pragma unroll
                for (int nf = 0; nf < 4; nf++)
                    mma16816(acc[mi][nf], af[mi], bf[nf]);
        }
        __syncthreads();
        buf ^= 1;
    }

    int lr = lane >> 2, lc = (lane & 3) * 2;

    if constexpr (OUTMODE == 3) {
        // ELU + store
        #pragma unroll
        for (int mi = 0; mi < 2; mi++) {
            #pragma unroll
            for (int nf = 0; nf < 4; nf++) {
                int r0 = rowBase + wm * 32 + mi * 16 + lr;
                int cc = colBase + wn * 32 + nf * 8 + lc;
                float v0 = acc[mi][nf][0], v1 = acc[mi][nf][1];
                float v2 = acc[mi][nf][2], v3 = acc[mi][nf][3];
                v0 = v0 > 0.f ? v0 : expm1f(v0);
                v1 = v1 > 0.f ? v1 : expm1f(v1);
                v2 = v2 > 0.f ? v2 : expm1f(v2);
                v3 = v3 > 0.f ? v3 : expm1f(v3);
                if (r0 < M)
                    *(__half2*)(Ch + (size_t)r0 * ldc + cc) = __floats2half2_rn(v0, v1);
                if (r0 + 8 < M)
                    *(__half2*)(Ch + (size_t)(r0 + 8) * ldc + cc) = __floats2half2_rn(v2, v3);
            }
        }
    } else {
        // store + fused el2/er2 score epilogue
        float sel[4] = {0.f, 0.f, 0.f, 0.f};
        float ser[4] = {0.f, 0.f, 0.f, 0.f};
        #pragma unroll
        for (int mi = 0; mi < 2; mi++) {
            #pragma unroll
            for (int nf = 0; nf < 4; nf++) {
                int r0 = rowBase + wm * 32 + mi * 16 + lr;
                int cc = colBase + wn * 32 + nf * 8 + lc;
                float a0 = __ldg(&al[cc]),  a1 = __ldg(&al[cc + 1]);
                float r0a = __ldg(&ar[cc]), r1a = __ldg(&ar[cc + 1]);
                if (r0 < M)
                    *(__half2*)(Ch + (size_t)r0 * ldc + cc) =
                        __floats2half2_rn(acc[mi][nf][0], acc[mi][nf][1]);
                if (r0 + 8 < M)
                    *(__half2*)(Ch + (size_t)(r0 + 8) * ldc + cc) =
                        __floats2half2_rn(acc[mi][nf][2], acc[mi][nf][3]);
                sel[mi * 2]     += acc[mi][nf][0] * a0  + acc[mi][nf][1] * a1;
                sel[mi * 2 + 1] += acc[mi][nf][2] * a0  + acc[mi][nf][3] * a1;
                ser[mi * 2]     += acc[mi][nf][0] * r0a + acc[mi][nf][1] * r1a;
                ser[mi * 2 + 1] += acc[mi][nf][2] * r0a + acc[mi][nf][3] * r1a;
            }
        }
        #pragma unroll
        for (int q = 0; q < 4; q++) {
            sel[q] += __shfl_xor_sync(0xffffffffu, sel[q], 1);
            sel[q] += __shfl_xor_sync(0xffffffffu, sel[q], 2);
            ser[q] += __shfl_xor_sync(0xffffffffu, ser[q], 1);
            ser[q] += __shfl_xor_sync(0xffffffffu, ser[q], 2);
        }
        if ((lane & 3) == 0) {
            #pragma unroll
            for (int q = 0; q < 4; q++) {
                int r = rowBase + wm * 32 + (q >> 1) * 16 + (q & 1) * 8 + lr;
                if (r < M) {
                    atomicAdd(&g_el2[r], sel[q]);
                    atomicAdd(&g_er2[r], ser[q]);
                }
            }
        }
    }
}

// ---------------- launch 8: h1 = ELU(aggx_h @ W1_h), 4 batched GEMMs ----------------
__global__ __launch_bounds__(256) void k_gemmelu() {
    int h = blockIdx.z;
    gemm_body<128, 3>(g_aggx + h * 128, F1, g_w1h + h * 128, F1,
                      g_h1h + h * 128, F1, NN, nullptr, nullptr,
                      blockIdx.y * 128, blockIdx.x * 64);
}

// ---------------- launch 9: feat2 = h1 @ W2, fused el2/er2 scores ----------------
__global__ __launch_bounds__(256) void k_gemm2h(const float* __restrict__ al,
                                                const float* __restrict__ ar) {
    gemm_body<512, 2>(g_h1h, F1, g_w2h, F2, g_feat2h, F2, NN, al, ar,
                      blockIdx.y * 128, 0);
}

// ---------------- launch 10: layer2 edge weights (node-parallel) + 1/Σw ----------------
__global__ __launch_bounds__(256) void k_wgt2() {
    int n = blockIdx.x * 8 + (threadIdx.x >> 5);
    int lane = threadIdx.x & 31;
    if (n >= NN) return;
    int start = g_rowptr[n], end = g_rowptr[n + 1];
    float er = g_er2[n];
    float ws = 0.f;
    for (int k = start + lane; k < end; k += 32) {
        int s = __ldg(&g_ssrc[k]);
        float w = __expf(lrelu(__ldg(&g_el2[s]) + er));
        g_w2e[k] = w;
        ws += w;
    }
    #pragma unroll
    for (int o = 16; o > 0; o >>= 1) ws += __shfl_xor_sync(0xffffffffu, ws, o);
    if (lane == 0) g_iws2[n] = (end > start) ? 1.f / ws : 0.f;
}

// ---------------- launch 11: layer2 aggregation, pure gather -> d_out ----------------
__global__ __launch_bounds__(256) void k_agg2(float* __restrict__ out) {
    int n = blockIdx.x * 8 + (threadIdx.x >> 5);
    int lane = threadIdx.x & 31;
    if (n >= NN) return;
    int start = g_rowptr[n], end = g_rowptr[n + 1];
    float ax = 0.f, ay = 0.f;
    int k = start;
    // peel to 16B alignment
    for (; k < end && (k & 3); k++) {
        int s = __ldg(&g_ssrc[k]);
        float w = __ldg(&g_w2e[k]);
        uint32_t r = __ldg((const uint32_t*)(g_feat2h + (size_t)s * F2) + lane);
        float2 f = __half22float2(*(__half2*)&r);
        ax += w * f.x; ay += w * f.y;
    }
    for (; k + 7 < end; k += 8) {
        int4 sa = __ldg((const int4*)(g_ssrc + k));
        int4 sb = __ldg((const int4*)(g_ssrc + k + 4));
        float4 wa = __ldg((const float4*)(g_w2e + k));
        float4 wb = __ldg((const float4*)(g_w2e + k + 4));
        uint32_t r0 = __ldg((const uint32_t*)(g_feat2h + (size_t)sa.x * F2) + lane);
        uint32_t r1 = __ldg((const uint32_t*)(g_feat2h + (size_t)sa.y * F2) + lane);
        uint32_t r2 = __ldg((const uint32_t*)(g_feat2h + (size_t)sa.z * F2) + lane);
        uint32_t r3 = __ldg((const uint32_t*)(g_feat2h + (size_t)sa.w * F2) + lane);
        uint32_t r4 = __ldg((const uint32_t*)(g_feat2h + (size_t)sb.x * F2) + lane);
        uint32_t r5 = __ldg((const uint32_t*)(g_feat2h + (size_t)sb.y * F2) + lane);
        uint32_t r6 = __ldg((const uint32_t*)(g_feat2h + (size_t)sb.z * F2) + lane);
        uint32_t r7 = __ldg((const uint32_t*)(g_feat2h + (size_t)sb.w * F2) + lane);
        float2 f;
        f = __half22float2(*(__half2*)&r0); ax += wa.x * f.x; ay += wa.x * f.y;
        f = __half22float2(*(__half2*)&r1); ax += wa.y * f.x; ay += wa.y * f.y;
        f = __half22float2(*(__half2*)&r2); ax += wa.z * f.x; ay += wa.z * f.y;
        f = __half22float2(*(__half2*)&r3); ax += wa.w * f.x; ay += wa.w * f.y;
        f = __half22float2(*(__half2*)&r4); ax += wb.x * f.x; ay += wb.x * f.y;
        f = __half22float2(*(__half2*)&r5); ax += wb.y * f.x; ay += wb.y * f.y;
        f = __half22float2(*(__half2*)&r6); ax += wb.z * f.x; ay += wb.z * f.y;
        f = __half22float2(*(__half2*)&r7); ax += wb.w * f.x; ay += wb.w * f.y;
    }
    if (k + 3 < end) {
        int4 sa = __ldg((const int4*)(g_ssrc + k));
        float4 wa = __ldg((const float4*)(g_w2e + k));
        uint32_t r0 = __ldg((const uint32_t*)(g_feat2h + (size_t)sa.x * F2) + lane);
        uint32_t r1 = __ldg((const uint32_t*)(g_feat2h + (size_t)sa.y * F2) + lane);
        uint32_t r2 = __ldg((const uint32_t*)(g_feat2h + (size_t)sa.z * F2) + lane);
        uint32_t r3 = __ldg((const uint32_t*)(g_feat2h + (size_t)sa.w * F2) + lane);
        float2 f;
        f = __half22float2(*(__half2*)&r0); ax += wa.x * f.x; ay += wa.x * f.y;
        f = __half22float2(*(__half2*)&r1); ax += wa.y * f.x; ay += wa.y * f.y;
        f = __half22float2(*(__half2*)&r2); ax += wa.z * f.x; ay += wa.z * f.y;
        f = __half22float2(*(__half2*)&r3); ax += wa.w * f.x; ay += wa.w * f.y;
        k += 4;
    }
    for (; k < end; k++) {
        int s = __ldg(&g_ssrc[k]);
        float w = __ldg(&g_w2e[k]);
        uint32_t r = __ldg((const uint32_t*)(g_feat2h + (size_t)s * F2) + lane);
        float2 f = __half22float2(*(__half2*)&r);
        ax += w * f.x; ay += w * f.y;
    }
    float sv = g_iws2[n];
    *(float2*)(out + (size_t)n * F2 + lane * 2) = make_float2(ax * sv, ay * sv);
}

// ---------------- launch ----------------
extern "C" void kernel_launch(void* const* d_in, const int* in_sizes, int n_in,
                              void* d_out, int out_size) {
    const float* x   = (const float*)d_in[0];
    const float* W1  = (const float*)d_in[1];
    const float* al1 = (const float*)d_in[2];
    const float* ar1 = (const float*)d_in[3];
    const float* W2  = (const float*)d_in[4];
    const float* al2 = (const float*)d_in[5];
    const float* ar2 = (const float*)d_in[6];
    const void*  src = d_in[7];
    const void*  dst = d_in[8];
    float* out = (float*)d_out;

    const int WB = (NN + 7) / 8;                // 12500
    const int MTILES = (NN + 127) / 128;        // 782

    // 1: detect + zero deg / el2 / er2
    k_setup0<<<1 + (NN + 255) / 256, 256>>>((const long long*)src);
    // 2: conv || cast || v-vector precompute
    k_setup1<<<EBLK * 2 + 8, 256>>>((const float4*)x, (const float4*)W1, (const float4*)W2,
                                    src, dst, al1, ar1);
    // 3: rowptr scan
    k_scan<<<1, 1024>>>();
    // 4: CSR scatter (src only)
    k_scatter<<<EBLK, 256>>>();
    // 5: layer1 scores from v-vectors
    k_score1<<<WB, 256>>>();
    // 6: layer1 edge weights (node-parallel, half2 quads) + 1/Σw
    k_wgt<<<WB, 256>>>();
    // 7: aggregate x — HFMA2 gather loop
    k_aggx<<<WB, 256>>>();
    // 8: h1 = ELU(aggx @ W1) — 4 batched 128-wide GEMMs
    k_gemmelu<<<dim3(2, MTILES, 4), 256>>>();
    // 9: feat2 = h1 @ W2 + fused scores
    k_gemm2h<<<dim3(1, MTILES), 256>>>(al2, ar2);
    // 10: layer2 edge weights (node-parallel) + 1/Σw
    k_wgt2<<<WB, 256>>>();
    // 11: layer2 aggregation — pure gather -> out
    k_agg2<<<WB, 256>>>(out);
}